// round 13
// baseline (speedup 1.0000x reference)
#include <cuda_runtime.h>
#include <cuda_bf16.h>
#include <cuda_fp16.h>
#include <math.h>

typedef unsigned long long ull;
typedef unsigned int u32;

// Problem constants
#define NB   16
#define CIN  128
#define COUT 128
#define HH   64
#define WW   64
#define HO   64
#define WO   64
#define PP   9
#define HW   (HH*WW)
#define PIX_PER_N (HO*WO)

#define ROWB 272   // smem row stride (136 f16 = 17*16B, conflict-free ldmatrix)

// ---------------- scratch ----------------
__device__ __align__(16) __half g_xh[NB * HH * WW * CIN];   // NHWC x, fp16
__device__ __align__(16) __half g_wf[PP * COUT * CIN];      // [p][cout][cin] fp16 (deform)
__device__ __align__(16) __half g_wo[PP * 32 * CIN];        // [p][cout_pad32][cin] fp16 (offset)
__device__ uint4 g_m[NB * PP * PIX_PER_N * 2];              // per idx: {ma, mw} interleaved

// ---------------- helpers ----------------
__device__ __forceinline__ u32 cvta_smem(const void* p) {
    u32 r;
    asm("{ .reg .u64 t; cvta.to.shared.u64 t, %1; cvt.u32.u64 %0, t; }" : "=r"(r) : "l"(p));
    return r;
}
__device__ __forceinline__ void ldm4(u32* r, u32 addr) {
    asm volatile("ldmatrix.sync.aligned.m8n8.x4.shared.b16 {%0,%1,%2,%3}, [%4];"
                 : "=r"(r[0]), "=r"(r[1]), "=r"(r[2]), "=r"(r[3]) : "r"(addr));
}
__device__ __forceinline__ void mma_f16(float* c, const u32* a, u32 b0, u32 b1) {
    asm volatile("mma.sync.aligned.m16n8k16.row.col.f32.f16.f16.f32 "
                 "{%0,%1,%2,%3}, {%4,%5,%6,%7}, {%8,%9}, {%0,%1,%2,%3};"
                 : "+f"(c[0]), "+f"(c[1]), "+f"(c[2]), "+f"(c[3])
                 : "r"(a[0]), "r"(a[1]), "r"(a[2]), "r"(a[3]), "r"(b0), "r"(b1));
}
__device__ __forceinline__ void cp_async16(u32 dst, const void* src) {
    asm volatile("cp.async.cg.shared.global [%0], [%1], 16;" :: "r"(dst), "l"(src));
}
__device__ __forceinline__ void cp_async16z(u32 dst, const void* src, u32 srcsz) {
    asm volatile("cp.async.cg.shared.global [%0], [%1], 16, %2;" :: "r"(dst), "l"(src), "r"(srcsz));
}
#define CP_COMMIT()  asm volatile("cp.async.commit_group;" ::: "memory")
#define CP_WAIT(n)   asm volatile("cp.async.wait_group %0;" :: "n"(n) : "memory")

// ---------------- kernel 1: x NCHW fp32 -> NHWC fp16 (vectorized) ----------------
// block: 32 channels x 64 hw, 256 threads, tile pad 67 (conflict-free both phases)
__global__ void k_transpose_x(const float* __restrict__ x) {
    __shared__ float tile[32][67];
    int n   = blockIdx.z;
    int hw0 = blockIdx.x * 64;
    int c0  = blockIdx.y * 32;
    int tid = threadIdx.x;
    #pragma unroll
    for (int i = 0; i < 2; i++) {
        int idx  = tid + i * 256;
        int row  = idx >> 4;          // channel 0..31
        int col4 = idx & 15;          // float4 along hw
        const float4* src = (const float4*)(x + ((size_t)(n * CIN + c0 + row)) * HW + hw0);
        float4 v = src[col4];
        tile[row][col4 * 4 + 0] = v.x;
        tile[row][col4 * 4 + 1] = v.y;
        tile[row][col4 * 4 + 2] = v.z;
        tile[row][col4 * 4 + 3] = v.w;
    }
    __syncthreads();
    #pragma unroll
    for (int i = 0; i < 4; i++) {
        int idx = tid + i * 256;
        int hw  = idx >> 4;           // 0..63
        int cp  = idx & 15;           // channel pair
        __half2 h = __halves2half2(__float2half_rn(tile[2 * cp][hw]),
                                   __float2half_rn(tile[2 * cp + 1][hw]));
        *(__half2*)&g_xh[((size_t)(n * HW + hw0 + hw)) * CIN + c0 + 2 * cp] = h;
    }
}

// ---------------- kernel 2: merged weight prep ----------------
__global__ void k_prep(const float* __restrict__ wf_src, const float* __restrict__ wo_src) {
    int i = blockIdx.x * 256 + threadIdx.x;
    if (i < PP * COUT * CIN) {
        int cin  = i & 127;
        int cout = (i >> 7) & 127;
        int p    = i >> 14;
        g_wf[i] = __float2half_rn(wf_src[(cout * CIN + cin) * PP + p]);
    } else {
        int j = i - PP * COUT * CIN;
        if (j < PP * 32 * CIN) {
            int cin  = j & 127;
            int cout = (j >> 7) & 31;
            int p    = j >> 12;
            g_wo[j] = (cout < 18) ? __float2half_rn(wo_src[(cout * CIN + cin) * PP + p])
                                  : __ushort_as_half((unsigned short)0);
        }
    }
}

// ---------------- kernel 3: offset conv via fp16 mma (64px, 4 CTA/SM, pipelined) ---
// smem: As0[0,17408) As1[17408,34816) Bs0[34816,43520) Bs1[43520,52224)
// outs (64*33 floats = 8448B) aliases As0 after the mainloop.
#define O_AS0 0
#define O_AS1 17408
#define O_BS0 34816
#define O_BS1 43520
#define SMEM_OFF 52224

__device__ __forceinline__ void off_issue(int p, int buf, int tid, int ho,
                                          const __half* xn, u32 sbase) {
    u32 asb = sbase + (buf ? O_AS1 : O_AS0);
    u32 bsb = sbase + (buf ? O_BS1 : O_BS0);
    int ky = p / 3 - 1, kx = p % 3 - 1;
    int ih = ho + ky;
    bool vrow = (unsigned)ih < 64u;
    #pragma unroll
    for (int i = 0; i < 4; i++) {
        int c   = tid + i * 256;
        int wo  = c >> 4, c16 = c & 15;
        int iw = wo + kx;
        bool v = vrow && ((unsigned)iw < 64u);
        int iwc = v ? iw : 0;
        int ihc = vrow ? ih : 0;
        const char* src = (const char*)(xn + ((size_t)(ihc * WW + iwc)) * CIN) + c16 * 16;
        cp_async16z(asb + (u32)(wo * ROWB + c16 * 16), src, v ? 16u : 0u);
    }
    #pragma unroll
    for (int i = 0; i < 2; i++) {
        int c   = tid + i * 256;
        int row = c >> 4, c16 = c & 15;
        cp_async16(bsb + (u32)(row * ROWB + c16 * 16),
                   (const char*)(g_wo + p * 32 * CIN) + row * 256 + c16 * 16);
    }
    CP_COMMIT();
}

__global__ __launch_bounds__(256, 4)
void k_offmma(const float* __restrict__ offset_b) {
    extern __shared__ char smc[];
    u32 sbase = cvta_smem(smc);
    float* outs = (float*)smc;      // alias As0 after mainloop

    int tid  = threadIdx.x;
    int ho   = blockIdx.x;
    int n    = blockIdx.y;
    int lane = tid & 31;
    int warp = tid >> 5;
    int wm   = warp >> 1;      // 0..3 (16-px groups)
    int wn   = warp & 1;       // 0..1 (16-co groups)
    int lrow = lane & 15;
    int lcol = (lane >> 4) << 4;

    float acc[2][4];
    #pragma unroll
    for (int nt = 0; nt < 2; nt++)
        #pragma unroll
        for (int i = 0; i < 4; i++) acc[nt][i] = 0.f;

    const __half* xn = g_xh + (size_t)n * HW * CIN;

    off_issue(0, 0, tid, ho, xn, sbase);       // C_{-1}

    for (int p = 0; p < PP; p++) {
        if (p < PP - 1) {
            off_issue(p + 1, (p + 1) & 1, tid, ho, xn, sbase);   // C_p
            CP_WAIT(1);                                          // drain C_{p-1}
        } else {
            CP_WAIT(0);
        }
        __syncthreads();

        u32 asU = sbase + ((p & 1) ? O_AS1 : O_AS0);
        u32 bsU = sbase + ((p & 1) ? O_BS1 : O_BS0);
        #pragma unroll
        for (int ks = 0; ks < 8; ks++) {
            u32 k0b = (u32)(ks * 32 + lcol);
            u32 a[4], b[4];
            ldm4(a, asU + (u32)((wm * 16 + lrow) * ROWB) + k0b);
            ldm4(b, bsU + (u32)((wn * 16 + lrow) * ROWB) + k0b);
            mma_f16(acc[0], a, b[0], b[2]);
            mma_f16(acc[1], a, b[1], b[3]);
        }
        __syncthreads();
    }

    // write acc -> outs[wo][co] (stride 33), outs aliases As0 (safe post-sync)
    #pragma unroll
    for (int nt = 0; nt < 2; nt++) {
        int co = wn * 16 + nt * 8 + (lane & 3) * 2;
        int px = wm * 16 + (lane >> 2);
        #pragma unroll
        for (int h = 0; h < 2; h++) {
            int pr = px + h * 8;
            outs[pr * 33 + co]     = acc[nt][h * 2 + 0];
            outs[pr * 33 + co + 1] = acc[nt][h * 2 + 1];
        }
    }
    __syncthreads();

    // metadata: clamped byte offsets + validity-folded half2 weights
    for (int it = tid; it < 64 * PP; it += 256) {
        int p  = it >> 6;
        int wo = it & 63;
        float dy = outs[wo * 33 + 2 * p]     + offset_b[2 * p];
        float dx = outs[wo * 33 + 2 * p + 1] + offset_b[2 * p + 1];
        float py  = dy + (float)(p / 3) + (float)(ho - 1);
        float pxx = dx + (float)(p % 3) + (float)(wo - 1);
        float y0f = floorf(py), x0f = floorf(pxx);
        float wy = py - y0f, wx = pxx - x0f;
        int y0 = (int)y0f, x0 = (int)x0f;
        bool vy0 = (unsigned)y0       < 64u;
        bool vy1 = (unsigned)(y0 + 1) < 64u;
        bool vx0 = (unsigned)x0       < 64u;
        bool vx1 = (unsigned)(x0 + 1) < 64u;
        float w00 = (vy0 && vx0) ? (1.f - wy) * (1.f - wx) : 0.f;
        float w01 = (vy0 && vx1) ? (1.f - wy) * wx         : 0.f;
        float w10 = (vy1 && vx0) ? wy * (1.f - wx)         : 0.f;
        float w11 = (vy1 && vx1) ? wy * wx                 : 0.f;
        int y0c = min(max(y0, 0), 63),     y1c = min(max(y0 + 1, 0), 63);
        int x0c = min(max(x0, 0), 63),     x1c = min(max(x0 + 1, 0), 63);
        uint4 ma = make_uint4((u32)(y0c * (WW * CIN * 2)), (u32)(y1c * (WW * CIN * 2)),
                              (u32)(x0c * (CIN * 2)),      (u32)(x1c * (CIN * 2)));
        __half2 h00 = __float2half2_rn(w00);
        __half2 h01 = __float2half2_rn(w01);
        __half2 h10 = __float2half2_rn(w10);
        __half2 h11 = __float2half2_rn(w11);
        uint4 mw = make_uint4(*(u32*)&h00, *(u32*)&h01, *(u32*)&h10, *(u32*)&h11);
        size_t idx = ((size_t)(n * PP + p)) * PIX_PER_N + ho * WO + wo;
        g_m[2 * idx]     = ma;
        g_m[2 * idx + 1] = mw;
    }
}

// ---------------- kernel 4: fully pipelined gather + fp16 mma + BN + SiLU ----------
// 256 threads, tile = one ho row: 64 px x 128 co. 2 CTAs/SM, Bs double-buffered.
// smem: As0 0, As1 17408, Bs0 34816, Bs1 69632, M0 104448, M1 106496,
//       ssh 108544, bsh 109056  -> total 109568
#define OFF_AS0  0
#define OFF_AS1  17408
#define OFF_BS0  34816
#define OFF_BS1  69632
#define OFF_M0   104448
#define OFF_M1   106496
#define OFF_SSH  108544
#define OFF_BBH  109056
#define SMEM_MAIN 109568

__device__ __forceinline__ void gather_px(int buf, int pix, int lane,
                                          const char* smc, const char* xb, char* smw) {
    const uint4* meta = (const uint4*)(smc + (buf ? OFF_M1 : OFF_M0));
    uint4 ma = meta[2 * pix];
    uint4 mw = meta[2 * pix + 1];
    int ch0 = lane * 4;
    const char* xc = xb + ch0 * 2;
    ull c00 = *(const ull*)(xc + ma.x + ma.z);
    ull c01 = *(const ull*)(xc + ma.x + ma.w);
    ull c10 = *(const ull*)(xc + ma.y + ma.z);
    ull c11 = *(const ull*)(xc + ma.y + ma.w);
    __half2 w00 = *(__half2*)&mw.x;
    __half2 w01 = *(__half2*)&mw.y;
    __half2 w10 = *(__half2*)&mw.z;
    __half2 w11 = *(__half2*)&mw.w;

    __half2 aL = __float2half2_rn(0.f), aH = aL;
    aL = __hfma2(w00, ((const __half2*)&c00)[0], aL);
    aH = __hfma2(w00, ((const __half2*)&c00)[1], aH);
    aL = __hfma2(w01, ((const __half2*)&c01)[0], aL);
    aH = __hfma2(w01, ((const __half2*)&c01)[1], aH);
    aL = __hfma2(w10, ((const __half2*)&c10)[0], aL);
    aH = __hfma2(w10, ((const __half2*)&c10)[1], aH);
    aL = __hfma2(w11, ((const __half2*)&c11)[0], aL);
    aH = __hfma2(w11, ((const __half2*)&c11)[1], aH);

    u32 lo = *(const u32*)&aL;
    u32 hi = *(const u32*)&aH;
    *(ull*)(smw + (buf ? OFF_AS1 : OFF_AS0) + pix * ROWB + ch0 * 2) = ((ull)hi << 32) | (ull)lo;
}

__device__ __forceinline__ void copy_bs(const __half* src_g, u32 dst_u, int tid) {
    const char* src = (const char*)src_g;
    #pragma unroll
    for (int i = 0; i < 8; i++) {
        int c   = tid + i * 256;
        int row = c >> 4;
        int c16 = c & 15;
        cp_async16(dst_u + (u32)(row * ROWB + c16 * 16), src + row * 256 + c16 * 16);
    }
}

__global__ __launch_bounds__(256, 2)
void k_main(const float* __restrict__ gamma,
            const float* __restrict__ beta,
            const float* __restrict__ rmean,
            const float* __restrict__ rvar,
            float* __restrict__ out) {
    extern __shared__ char smc[];
    float* ssh  = (float*)(smc + OFF_SSH);
    float* bsh  = (float*)(smc + OFF_BBH);
    u32 sbase = cvta_smem(smc);

    int tid  = threadIdx.x;
    int ho   = blockIdx.x;
    int n    = blockIdx.y;
    int lane = tid & 31;
    int warp = tid >> 5;
    int wm   = warp >> 2;
    int wn   = warp & 3;
    int gpix0 = warp * 8;

    const char* mbase0 = (const char*)(g_m + 2 * (((size_t)(n * PP)) * PIX_PER_N + ho * WO));
    const size_t mstride = (size_t)PIX_PER_N * 32;

    if (tid < COUT) {
        float s = gamma[tid] * rsqrtf(rvar[tid] + 1e-5f);
        ssh[tid] = s;
        bsh[tid] = beta[tid] - rmean[tid] * s;
    }

    const char* xb = (const char*)(g_xh + (size_t)n * HW * CIN);

    // prologue:
    // G      = {meta(0) -> M0}
    // C_{-1} = {Bs(0) -> Bs0, meta(1) -> M1}
    if (tid < 128) cp_async16(sbase + OFF_M0 + tid * 16, mbase0 + tid * 16);
    CP_COMMIT();
    copy_bs(g_wf, sbase + OFF_BS0, tid);
    if (tid < 128) cp_async16(sbase + OFF_M1 + tid * 16, mbase0 + mstride + tid * 16);
    CP_COMMIT();
    CP_WAIT(1);                 // G done (meta0)
    __syncthreads();
    #pragma unroll 4
    for (int pl = 0; pl < 8; pl++)
        gather_px(0, gpix0 + pl, lane, smc, xb, smc);
    __syncthreads();            // As0 visible; M0 free for reuse

    float acc[2][4][4];
    #pragma unroll
    for (int mt = 0; mt < 2; mt++)
        #pragma unroll
        for (int nt = 0; nt < 4; nt++)
            #pragma unroll
            for (int i = 0; i < 4; i++) acc[mt][nt][i] = 0.f;

    int lrow = lane & 15;
    int lcol = (lane >> 4) << 4;

    for (int p = 0; p < PP; p++) {
        // C_p = {Bs(p+1) -> bbuf((p+1)&1), meta(p+2) -> mbuf(p&1)}
        if (p < PP - 1) {
            copy_bs(g_wf + (size_t)(p + 1) * COUT * CIN,
                    sbase + (((p + 1) & 1) ? OFF_BS1 : OFF_BS0), tid);
            if (p + 2 < PP && tid < 128)
                cp_async16(sbase + ((p & 1) ? OFF_M1 : OFF_M0) + tid * 16,
                           mbase0 + (size_t)(p + 2) * mstride + tid * 16);
            CP_COMMIT();
            CP_WAIT(1);          // drain C_{p-1}: Bs(p), meta(p+1)
        } else {
            CP_WAIT(0);          // drain C_{PP-2}: Bs(PP-1)
        }
        __syncthreads();

        // gather(p+1) into As((p+1)&1) using meta buf (p+1)&1
        if (p < PP - 1) {
            #pragma unroll 4
            for (int pl = 0; pl < 8; pl++)
                gather_px((p + 1) & 1, gpix0 + pl, lane, smc, xb, smc);
        }

        // GEMM tap p
        u32 asb = sbase + ((p & 1) ? OFF_AS1 : OFF_AS0);
        u32 bsb = sbase + ((p & 1) ? OFF_BS1 : OFF_BS0);
        #pragma unroll
        for (int ks = 0; ks < 8; ks++) {
            u32 k0b = (u32)(ks * 32 + lcol);
            u32 a[2][4], b[2][4];
            #pragma unroll
            for (int mt = 0; mt < 2; mt++)
                ldm4(a[mt], asb + (u32)((wm * 32 + mt * 16 + lrow) * ROWB) + k0b);
            #pragma unroll
            for (int pr = 0; pr < 2; pr++)
                ldm4(b[pr], bsb + (u32)((wn * 32 + pr * 16 + lrow) * ROWB) + k0b);
            #pragma unroll
            for (int mt = 0; mt < 2; mt++)
                #pragma unroll
                for (int nt = 0; nt < 4; nt++) {
                    int pr = nt >> 1, s = nt & 1;
                    mma_f16(acc[mt][nt], a[mt], b[pr][s], b[pr][2 + s]);
                }
        }
        __syncthreads();         // readers of As(p&1)/Bs(p&1)/M((p+1)&1) done; STS drained
    }

    // ---- epilogue: BN + SiLU ----
    #pragma unroll
    for (int mt = 0; mt < 2; mt++)
        #pragma unroll
        for (int nt = 0; nt < 4; nt++) {
            int co = wn * 32 + nt * 8 + (lane & 3) * 2;
            int px = wm * 32 + mt * 16 + (lane >> 2);
            float s0 = ssh[co],     b0 = bsh[co];
            float s1 = ssh[co + 1], b1 = bsh[co + 1];
            #pragma unroll
            for (int h = 0; h < 2; h++) {
                int wo = px + h * 8;
                float y0v = acc[mt][nt][h * 2 + 0] * s0 + b0;
                float y1v = acc[mt][nt][h * 2 + 1] * s1 + b1;
                out[(((size_t)(n * COUT + co))     * HO + ho) * WO + wo] = y0v / (1.f + __expf(-y0v));
                out[(((size_t)(n * COUT + co + 1)) * HO + ho) * WO + wo] = y1v / (1.f + __expf(-y1v));
            }
        }
}

// ---------------- launch ----------------
extern "C" void kernel_launch(void* const* d_in, const int* in_sizes, int n_in,
                              void* d_out, int out_size) {
    const float* x        = (const float*)d_in[0];
    const float* offset_w = (const float*)d_in[1];
    const float* offset_b = (const float*)d_in[2];
    const float* deform_w = (const float*)d_in[3];
    const float* gamma    = (const float*)d_in[4];
    const float* beta     = (const float*)d_in[5];
    const float* rmean    = (const float*)d_in[6];
    const float* rvar     = (const float*)d_in[7];
    float* out = (float*)d_out;

    cudaFuncSetAttribute(k_offmma, cudaFuncAttributeMaxDynamicSharedMemorySize, SMEM_OFF);
    cudaFuncSetAttribute(k_main,   cudaFuncAttributeMaxDynamicSharedMemorySize, SMEM_MAIN);

    k_transpose_x<<<dim3(HW / 64, CIN / 32, NB), 256>>>(x);
    k_prep<<<(PP * COUT * CIN + PP * 32 * CIN + 255) / 256, 256>>>(deform_w, offset_w);

    k_offmma<<<dim3(HO, NB), 256, SMEM_OFF>>>(offset_b);

    k_main<<<dim3(HO, NB), 256, SMEM_MAIN>>>(gamma, beta, rmean, rvar, out);
}

// round 14
// speedup vs baseline: 1.0661x; 1.0661x over previous
#include <cuda_runtime.h>
#include <cuda_bf16.h>
#include <cuda_fp16.h>
#include <math.h>

typedef unsigned long long ull;
typedef unsigned int u32;

// Problem constants
#define NB   16
#define CIN  128
#define COUT 128
#define HH   64
#define WW   64
#define HO   64
#define WO   64
#define PP   9
#define HW   (HH*WW)
#define PIX_PER_N (HO*WO)

#define ROWB 272   // smem row stride (136 f16 = 17*16B, conflict-free ldmatrix)

// ---------------- scratch ----------------
__device__ __align__(16) __half g_xh[NB * HH * WW * CIN];   // NHWC x, fp16
__device__ __align__(16) __half g_wf[PP * COUT * CIN];      // [p][cout][cin] fp16 (deform)
__device__ __align__(16) __half g_wo[PP * 32 * CIN];        // [p][cout_pad32][cin] fp16 (offset)
__device__ uint4 g_m[NB * PP * PIX_PER_N * 2];              // per idx: {ma, mw} interleaved

// ---------------- helpers ----------------
__device__ __forceinline__ u32 cvta_smem(const void* p) {
    u32 r;
    asm("{ .reg .u64 t; cvta.to.shared.u64 t, %1; cvt.u32.u64 %0, t; }" : "=r"(r) : "l"(p));
    return r;
}
__device__ __forceinline__ void ldm4(u32* r, u32 addr) {
    asm volatile("ldmatrix.sync.aligned.m8n8.x4.shared.b16 {%0,%1,%2,%3}, [%4];"
                 : "=r"(r[0]), "=r"(r[1]), "=r"(r[2]), "=r"(r[3]) : "r"(addr));
}
__device__ __forceinline__ void mma_f16(float* c, const u32* a, u32 b0, u32 b1) {
    asm volatile("mma.sync.aligned.m16n8k16.row.col.f32.f16.f16.f32 "
                 "{%0,%1,%2,%3}, {%4,%5,%6,%7}, {%8,%9}, {%0,%1,%2,%3};"
                 : "+f"(c[0]), "+f"(c[1]), "+f"(c[2]), "+f"(c[3])
                 : "r"(a[0]), "r"(a[1]), "r"(a[2]), "r"(a[3]), "r"(b0), "r"(b1));
}
__device__ __forceinline__ void cp_async16(u32 dst, const void* src) {
    asm volatile("cp.async.cg.shared.global [%0], [%1], 16;" :: "r"(dst), "l"(src));
}
__device__ __forceinline__ void cp_async16z(u32 dst, const void* src, u32 srcsz) {
    asm volatile("cp.async.cg.shared.global [%0], [%1], 16, %2;" :: "r"(dst), "l"(src), "r"(srcsz));
}
#define CP_COMMIT()  asm volatile("cp.async.commit_group;" ::: "memory")
#define CP_WAIT(n)   asm volatile("cp.async.wait_group %0;" :: "n"(n) : "memory")

// ---------------- kernel 1: x NCHW fp32 -> NHWC fp16 (vectorized) ----------------
__global__ void k_transpose_x(const float* __restrict__ x) {
    __shared__ float tile[32][67];
    int n   = blockIdx.z;
    int hw0 = blockIdx.x * 64;
    int c0  = blockIdx.y * 32;
    int tid = threadIdx.x;
    #pragma unroll
    for (int i = 0; i < 2; i++) {
        int idx  = tid + i * 256;
        int row  = idx >> 4;          // channel 0..31
        int col4 = idx & 15;          // float4 along hw
        const float4* src = (const float4*)(x + ((size_t)(n * CIN + c0 + row)) * HW + hw0);
        float4 v = src[col4];
        tile[row][col4 * 4 + 0] = v.x;
        tile[row][col4 * 4 + 1] = v.y;
        tile[row][col4 * 4 + 2] = v.z;
        tile[row][col4 * 4 + 3] = v.w;
    }
    __syncthreads();
    #pragma unroll
    for (int i = 0; i < 4; i++) {
        int idx = tid + i * 256;
        int hw  = idx >> 4;           // 0..63
        int cp  = idx & 15;           // channel pair
        __half2 h = __halves2half2(__float2half_rn(tile[2 * cp][hw]),
                                   __float2half_rn(tile[2 * cp + 1][hw]));
        *(__half2*)&g_xh[((size_t)(n * HW + hw0 + hw)) * CIN + c0 + 2 * cp] = h;
    }
}

// ---------------- kernel 2: merged weight prep ----------------
__global__ void k_prep(const float* __restrict__ wf_src, const float* __restrict__ wo_src) {
    int i = blockIdx.x * 256 + threadIdx.x;
    if (i < PP * COUT * CIN) {
        int cin  = i & 127;
        int cout = (i >> 7) & 127;
        int p    = i >> 14;
        g_wf[i] = __float2half_rn(wf_src[(cout * CIN + cin) * PP + p]);
    } else {
        int j = i - PP * COUT * CIN;
        if (j < PP * 32 * CIN) {
            int cin  = j & 127;
            int cout = (j >> 7) & 31;
            int p    = j >> 12;
            g_wo[j] = (cout < 18) ? __float2half_rn(wo_src[(cout * CIN + cin) * PP + p])
                                  : __ushort_as_half((unsigned short)0);
        }
    }
}

// ---------------- kernel 3: offset conv via fp16 mma (64px, 4 CTA/SM, pipelined) ---
#define O_AS0 0
#define O_AS1 17408
#define O_BS0 34816
#define O_BS1 43520
#define SMEM_OFF 52224

__device__ __forceinline__ void off_issue(int p, int buf, int tid, int ho,
                                          const __half* xn, u32 sbase) {
    u32 asb = sbase + (buf ? O_AS1 : O_AS0);
    u32 bsb = sbase + (buf ? O_BS1 : O_BS0);
    int ky = p / 3 - 1, kx = p % 3 - 1;
    int ih = ho + ky;
    bool vrow = (unsigned)ih < 64u;
    #pragma unroll
    for (int i = 0; i < 4; i++) {
        int c   = tid + i * 256;
        int wo  = c >> 4, c16 = c & 15;
        int iw = wo + kx;
        bool v = vrow && ((unsigned)iw < 64u);
        int iwc = v ? iw : 0;
        int ihc = vrow ? ih : 0;
        const char* src = (const char*)(xn + ((size_t)(ihc * WW + iwc)) * CIN) + c16 * 16;
        cp_async16z(asb + (u32)(wo * ROWB + c16 * 16), src, v ? 16u : 0u);
    }
    #pragma unroll
    for (int i = 0; i < 2; i++) {
        int c   = tid + i * 256;
        int row = c >> 4, c16 = c & 15;
        cp_async16(bsb + (u32)(row * ROWB + c16 * 16),
                   (const char*)(g_wo + p * 32 * CIN) + row * 256 + c16 * 16);
    }
    CP_COMMIT();
}

__global__ __launch_bounds__(256, 4)
void k_offmma(const float* __restrict__ offset_b) {
    extern __shared__ char smc[];
    u32 sbase = cvta_smem(smc);
    float* outs = (float*)smc;      // alias As0 after mainloop

    int tid  = threadIdx.x;
    int ho   = blockIdx.x;
    int n    = blockIdx.y;
    int lane = tid & 31;
    int warp = tid >> 5;
    int wm   = warp >> 1;      // 0..3 (16-px groups)
    int wn   = warp & 1;       // 0..1 (16-co groups)
    int lrow = lane & 15;
    int lcol = (lane >> 4) << 4;

    float acc[2][4];
    #pragma unroll
    for (int nt = 0; nt < 2; nt++)
        #pragma unroll
        for (int i = 0; i < 4; i++) acc[nt][i] = 0.f;

    const __half* xn = g_xh + (size_t)n * HW * CIN;

    off_issue(0, 0, tid, ho, xn, sbase);       // C_{-1}

    for (int p = 0; p < PP; p++) {
        if (p < PP - 1) {
            off_issue(p + 1, (p + 1) & 1, tid, ho, xn, sbase);   // C_p
            CP_WAIT(1);                                          // drain C_{p-1}
        } else {
            CP_WAIT(0);
        }
        __syncthreads();

        u32 asU = sbase + ((p & 1) ? O_AS1 : O_AS0);
        u32 bsU = sbase + ((p & 1) ? O_BS1 : O_BS0);
        #pragma unroll
        for (int ks = 0; ks < 8; ks++) {
            u32 k0b = (u32)(ks * 32 + lcol);
            u32 a[4], b[4];
            ldm4(a, asU + (u32)((wm * 16 + lrow) * ROWB) + k0b);
            ldm4(b, bsU + (u32)((wn * 16 + lrow) * ROWB) + k0b);
            mma_f16(acc[0], a, b[0], b[2]);
            mma_f16(acc[1], a, b[1], b[3]);
        }
        __syncthreads();
    }

    // write acc -> outs[wo][co] (stride 33), outs aliases As0 (safe post-sync)
    #pragma unroll
    for (int nt = 0; nt < 2; nt++) {
        int co = wn * 16 + nt * 8 + (lane & 3) * 2;
        int px = wm * 16 + (lane >> 2);
        #pragma unroll
        for (int h = 0; h < 2; h++) {
            int pr = px + h * 8;
            outs[pr * 33 + co]     = acc[nt][h * 2 + 0];
            outs[pr * 33 + co + 1] = acc[nt][h * 2 + 1];
        }
    }
    __syncthreads();

    // metadata: clamped byte offsets + validity-folded half2 weights
    for (int it = tid; it < 64 * PP; it += 256) {
        int p  = it >> 6;
        int wo = it & 63;
        float dy = outs[wo * 33 + 2 * p]     + offset_b[2 * p];
        float dx = outs[wo * 33 + 2 * p + 1] + offset_b[2 * p + 1];
        float py  = dy + (float)(p / 3) + (float)(ho - 1);
        float pxx = dx + (float)(p % 3) + (float)(wo - 1);
        float y0f = floorf(py), x0f = floorf(pxx);
        float wy = py - y0f, wx = pxx - x0f;
        int y0 = (int)y0f, x0 = (int)x0f;
        bool vy0 = (unsigned)y0       < 64u;
        bool vy1 = (unsigned)(y0 + 1) < 64u;
        bool vx0 = (unsigned)x0       < 64u;
        bool vx1 = (unsigned)(x0 + 1) < 64u;
        float w00 = (vy0 && vx0) ? (1.f - wy) * (1.f - wx) : 0.f;
        float w01 = (vy0 && vx1) ? (1.f - wy) * wx         : 0.f;
        float w10 = (vy1 && vx0) ? wy * (1.f - wx)         : 0.f;
        float w11 = (vy1 && vx1) ? wy * wx                 : 0.f;
        int y0c = min(max(y0, 0), 63),     y1c = min(max(y0 + 1, 0), 63);
        int x0c = min(max(x0, 0), 63),     x1c = min(max(x0 + 1, 0), 63);
        uint4 ma = make_uint4((u32)(y0c * (WW * CIN * 2)), (u32)(y1c * (WW * CIN * 2)),
                              (u32)(x0c * (CIN * 2)),      (u32)(x1c * (CIN * 2)));
        __half2 h00 = __float2half2_rn(w00);
        __half2 h01 = __float2half2_rn(w01);
        __half2 h10 = __float2half2_rn(w10);
        __half2 h11 = __float2half2_rn(w11);
        uint4 mw = make_uint4(*(u32*)&h00, *(u32*)&h01, *(u32*)&h10, *(u32*)&h11);
        size_t idx = ((size_t)(n * PP + p)) * PIX_PER_N + ho * WO + wo;
        g_m[2 * idx]     = ma;
        g_m[2 * idx + 1] = mw;
    }
}

// ---------------- kernel 4: pipelined gather + fp16 mma + BN + SiLU (R12 version) --
// 256 threads, tile = one ho row: 64 px x 128 co. 3 CTAs/SM.
// smem: As[2][17408] at 0, Bs at 34816, meta[2][2048] at 69632,
//       ssh at 73728, bsh at 74240  -> total 74752
#define OFF_AS   0
#define OFF_BS   34816
#define OFF_M    69632
#define OFF_SSH  73728
#define OFF_BBH  74240
#define SMEM_MAIN 74752

__device__ __forceinline__ void gather_px(int buf, int pix, int lane,
                                          const char* smc, const char* xb, char* smw) {
    const uint4* meta = (const uint4*)(smc + OFF_M + buf * 2048);
    uint4 ma = meta[2 * pix];
    uint4 mw = meta[2 * pix + 1];
    int ch0 = lane * 4;
    const char* xc = xb + ch0 * 2;
    ull c00 = *(const ull*)(xc + ma.x + ma.z);
    ull c01 = *(const ull*)(xc + ma.x + ma.w);
    ull c10 = *(const ull*)(xc + ma.y + ma.z);
    ull c11 = *(const ull*)(xc + ma.y + ma.w);
    __half2 w00 = *(__half2*)&mw.x;
    __half2 w01 = *(__half2*)&mw.y;
    __half2 w10 = *(__half2*)&mw.z;
    __half2 w11 = *(__half2*)&mw.w;

    __half2 aL = __float2half2_rn(0.f), aH = aL;
    aL = __hfma2(w00, ((const __half2*)&c00)[0], aL);
    aH = __hfma2(w00, ((const __half2*)&c00)[1], aH);
    aL = __hfma2(w01, ((const __half2*)&c01)[0], aL);
    aH = __hfma2(w01, ((const __half2*)&c01)[1], aH);
    aL = __hfma2(w10, ((const __half2*)&c10)[0], aL);
    aH = __hfma2(w10, ((const __half2*)&c10)[1], aH);
    aL = __hfma2(w11, ((const __half2*)&c11)[0], aL);
    aH = __hfma2(w11, ((const __half2*)&c11)[1], aH);

    u32 lo = *(const u32*)&aL;
    u32 hi = *(const u32*)&aH;
    *(ull*)(smw + OFF_AS + buf * 17408 + pix * ROWB + ch0 * 2) = ((ull)hi << 32) | (ull)lo;
}

__device__ __forceinline__ void copy_bs(const __half* src_g, u32 dst_u, int tid) {
    const char* src = (const char*)src_g;
    #pragma unroll
    for (int i = 0; i < 8; i++) {
        int c   = tid + i * 256;
        int row = c >> 4;
        int c16 = c & 15;
        cp_async16(dst_u + (u32)(row * ROWB + c16 * 16), src + row * 256 + c16 * 16);
    }
}

__global__ __launch_bounds__(256, 3)
void k_main(const float* __restrict__ gamma,
            const float* __restrict__ beta,
            const float* __restrict__ rmean,
            const float* __restrict__ rvar,
            float* __restrict__ out) {
    extern __shared__ char smc[];
    float* ssh  = (float*)(smc + OFF_SSH);
    float* bsh  = (float*)(smc + OFF_BBH);
    u32 sbase = cvta_smem(smc);
    u32 asU = sbase + OFF_AS;
    u32 bsU = sbase + OFF_BS;
    u32 mU  = sbase + OFF_M;

    int tid  = threadIdx.x;
    int ho   = blockIdx.x;
    int n    = blockIdx.y;
    int lane = tid & 31;
    int warp = tid >> 5;
    int wm   = warp >> 2;
    int wn   = warp & 3;
    int gpix0 = warp * 8;

    const char* mbase0 = (const char*)(g_m + 2 * (((size_t)(n * PP)) * PIX_PER_N + ho * WO));
    const size_t mstride = (size_t)PIX_PER_N * 32;

    if (tid < COUT) {
        float s = gamma[tid] * rsqrtf(rvar[tid] + 1e-5f);
        ssh[tid] = s;
        bsh[tid] = beta[tid] - rmean[tid] * s;
    }

    const char* xb = (const char*)(g_xh + (size_t)n * HW * CIN);

    // prologue: meta(0) + Bs(0); wait; gather(0); meta(1); wait
    if (tid < 128) cp_async16(mU + tid * 16, mbase0 + tid * 16);
    copy_bs(g_wf, bsU, tid);
    CP_COMMIT();
    CP_WAIT(0);
    __syncthreads();
    #pragma unroll 4
    for (int pl = 0; pl < 8; pl++)
        gather_px(0, gpix0 + pl, lane, smc, xb, smc);
    if (tid < 128) cp_async16(mU + 2048 + tid * 16, mbase0 + mstride + tid * 16);
    CP_COMMIT();
    CP_WAIT(0);
    __syncthreads();

    float acc[2][4][4];
    #pragma unroll
    for (int mt = 0; mt < 2; mt++)
        #pragma unroll
        for (int nt = 0; nt < 4; nt++)
            #pragma unroll
            for (int i = 0; i < 4; i++) acc[mt][nt][i] = 0.f;

    int lrow = lane & 15;
    int lcol = (lane >> 4) << 4;

    for (int p = 0; p < PP; p++) {
        // issue meta(p+2) into mbuf(p&1); gather(p+1) into As buf (p+1)&1
        if (p <= PP - 3) {
            if (tid < 128)
                cp_async16(mU + (p & 1) * 2048 + tid * 16,
                           mbase0 + (size_t)(p + 2) * mstride + tid * 16);
            CP_COMMIT();
        }
        if (p <= PP - 2) {
            #pragma unroll 4
            for (int pl = 0; pl < 8; pl++)
                gather_px((p + 1) & 1, gpix0 + pl, lane, smc, xb, smc);
        }

        // ---- GEMM tap p from As buf (p&1) ----
        u32 asb = asU + (u32)((p & 1) * 17408);
        #pragma unroll
        for (int ks = 0; ks < 8; ks++) {
            u32 k0b = (u32)(ks * 32 + lcol);
            u32 a[2][4], b[2][4];
            #pragma unroll
            for (int mt = 0; mt < 2; mt++)
                ldm4(a[mt], asb + (u32)((wm * 32 + mt * 16 + lrow) * ROWB) + k0b);
            #pragma unroll
            for (int pr = 0; pr < 2; pr++)
                ldm4(b[pr], bsU + (u32)((wn * 32 + pr * 16 + lrow) * ROWB) + k0b);
            #pragma unroll
            for (int mt = 0; mt < 2; mt++)
                #pragma unroll
                for (int nt = 0; nt < 4; nt++) {
                    int pr = nt >> 1, s = nt & 1;
                    mma_f16(acc[mt][nt], a[mt], b[pr][s], b[pr][2 + s]);
                }
        }
        __syncthreads();                 // done reading Bs(p) + As(p&1); gather STS drained
        if (p <= PP - 2) {
            copy_bs(g_wf + (size_t)(p + 1) * COUT * CIN, bsU, tid);
            CP_COMMIT();
            CP_WAIT(0);
            __syncthreads();
        }
    }

    // ---- epilogue: BN + SiLU ----
    #pragma unroll
    for (int mt = 0; mt < 2; mt++)
        #pragma unroll
        for (int nt = 0; nt < 4; nt++) {
            int co = wn * 32 + nt * 8 + (lane & 3) * 2;
            int px = wm * 32 + mt * 16 + (lane >> 2);
            float s0 = ssh[co],     b0 = bsh[co];
            float s1 = ssh[co + 1], b1 = bsh[co + 1];
            #pragma unroll
            for (int h = 0; h < 2; h++) {
                int wo = px + h * 8;
                float y0v = acc[mt][nt][h * 2 + 0] * s0 + b0;
                float y1v = acc[mt][nt][h * 2 + 1] * s1 + b1;
                out[(((size_t)(n * COUT + co))     * HO + ho) * WO + wo] = y0v / (1.f + __expf(-y0v));
                out[(((size_t)(n * COUT + co + 1)) * HO + ho) * WO + wo] = y1v / (1.f + __expf(-y1v));
            }
        }
}

// ---------------- launch ----------------
extern "C" void kernel_launch(void* const* d_in, const int* in_sizes, int n_in,
                              void* d_out, int out_size) {
    const float* x        = (const float*)d_in[0];
    const float* offset_w = (const float*)d_in[1];
    const float* offset_b = (const float*)d_in[2];
    const float* deform_w = (const float*)d_in[3];
    const float* gamma    = (const float*)d_in[4];
    const float* beta     = (const float*)d_in[5];
    const float* rmean    = (const float*)d_in[6];
    const float* rvar     = (const float*)d_in[7];
    float* out = (float*)d_out;

    cudaFuncSetAttribute(k_offmma, cudaFuncAttributeMaxDynamicSharedMemorySize, SMEM_OFF);
    cudaFuncSetAttribute(k_main,   cudaFuncAttributeMaxDynamicSharedMemorySize, SMEM_MAIN);

    k_transpose_x<<<dim3(HW / 64, CIN / 32, NB), 256>>>(x);
    k_prep<<<(PP * COUT * CIN + PP * 32 * CIN + 255) / 256, 256>>>(deform_w, offset_w);

    k_offmma<<<dim3(HO, NB), 256, SMEM_OFF>>>(offset_b);

    k_main<<<dim3(HO, NB), 256, SMEM_MAIN>>>(gamma, beta, rmean, rvar, out);
}

// round 15
// speedup vs baseline: 1.2050x; 1.1303x over previous
#include <cuda_runtime.h>
#include <cuda_bf16.h>
#include <cuda_fp16.h>
#include <math.h>

typedef unsigned long long ull;
typedef unsigned int u32;

// Problem constants
#define NB   16
#define CIN  128
#define COUT 128
#define HH   64
#define WW   64
#define HO   64
#define WO   64
#define PP   9
#define HW   (HH*WW)
#define PIX_PER_N (HO*WO)

#define ROWB 272   // smem row stride (136 f16 = 17*16B, conflict-free ldmatrix)

// ---------------- scratch ----------------
__device__ __align__(16) __half g_xh[NB * HH * WW * CIN];   // NHWC x, fp16
__device__ __align__(16) __half g_wf[PP * COUT * CIN];      // [p][cout][cin] fp16 (deform)
__device__ __align__(16) __half g_wo[PP * 32 * CIN];        // [p][cout_pad32][cin] fp16 (offset)
__device__ uint4 g_m[NB * PP * PIX_PER_N * 2];              // per idx: {ma, mw} interleaved

// ---------------- helpers ----------------
__device__ __forceinline__ u32 cvta_smem(const void* p) {
    u32 r;
    asm("{ .reg .u64 t; cvta.to.shared.u64 t, %1; cvt.u32.u64 %0, t; }" : "=r"(r) : "l"(p));
    return r;
}
__device__ __forceinline__ void ldm4(u32* r, u32 addr) {
    asm volatile("ldmatrix.sync.aligned.m8n8.x4.shared.b16 {%0,%1,%2,%3}, [%4];"
                 : "=r"(r[0]), "=r"(r[1]), "=r"(r[2]), "=r"(r[3]) : "r"(addr));
}
__device__ __forceinline__ void mma_f16(float* c, const u32* a, u32 b0, u32 b1) {
    asm volatile("mma.sync.aligned.m16n8k16.row.col.f32.f16.f16.f32 "
                 "{%0,%1,%2,%3}, {%4,%5,%6,%7}, {%8,%9}, {%0,%1,%2,%3};"
                 : "+f"(c[0]), "+f"(c[1]), "+f"(c[2]), "+f"(c[3])
                 : "r"(a[0]), "r"(a[1]), "r"(a[2]), "r"(a[3]), "r"(b0), "r"(b1));
}
__device__ __forceinline__ void cp_async16(u32 dst, const void* src) {
    asm volatile("cp.async.cg.shared.global [%0], [%1], 16;" :: "r"(dst), "l"(src));
}
__device__ __forceinline__ void cp_async16z(u32 dst, const void* src, u32 srcsz) {
    asm volatile("cp.async.cg.shared.global [%0], [%1], 16, %2;" :: "r"(dst), "l"(src), "r"(srcsz));
}
#define CP_COMMIT()  asm volatile("cp.async.commit_group;" ::: "memory")
#define CP_WAIT(n)   asm volatile("cp.async.wait_group %0;" :: "n"(n) : "memory")

// ---------------- kernel 1: x NCHW fp32 -> NHWC fp16 (vectorized) ----------------
__global__ void k_transpose_x(const float* __restrict__ x) {
    __shared__ float tile[32][67];
    int n   = blockIdx.z;
    int hw0 = blockIdx.x * 64;
    int c0  = blockIdx.y * 32;
    int tid = threadIdx.x;
    #pragma unroll
    for (int i = 0; i < 2; i++) {
        int idx  = tid + i * 256;
        int row  = idx >> 4;
        int col4 = idx & 15;
        const float4* src = (const float4*)(x + ((size_t)(n * CIN + c0 + row)) * HW + hw0);
        float4 v = src[col4];
        tile[row][col4 * 4 + 0] = v.x;
        tile[row][col4 * 4 + 1] = v.y;
        tile[row][col4 * 4 + 2] = v.z;
        tile[row][col4 * 4 + 3] = v.w;
    }
    __syncthreads();
    #pragma unroll
    for (int i = 0; i < 4; i++) {
        int idx = tid + i * 256;
        int hw  = idx >> 4;
        int cp  = idx & 15;
        __half2 h = __halves2half2(__float2half_rn(tile[2 * cp][hw]),
                                   __float2half_rn(tile[2 * cp + 1][hw]));
        *(__half2*)&g_xh[((size_t)(n * HW + hw0 + hw)) * CIN + c0 + 2 * cp] = h;
    }
}

// ---------------- kernel 2: merged weight prep ----------------
__global__ void k_prep(const float* __restrict__ wf_src, const float* __restrict__ wo_src) {
    int i = blockIdx.x * 256 + threadIdx.x;
    if (i < PP * COUT * CIN) {
        int cin  = i & 127;
        int cout = (i >> 7) & 127;
        int p    = i >> 14;
        g_wf[i] = __float2half_rn(wf_src[(cout * CIN + cin) * PP + p]);
    } else {
        int j = i - PP * COUT * CIN;
        if (j < PP * 32 * CIN) {
            int cin  = j & 127;
            int cout = (j >> 7) & 31;
            int p    = j >> 12;
            g_wo[j] = (cout < 18) ? __float2half_rn(wo_src[(cout * CIN + cin) * PP + p])
                                  : __ushort_as_half((unsigned short)0);
        }
    }
}

// ---------------- kernel 3: offset conv via fp16 mma (64px, 4 CTA/SM, pipelined) ---
#define O_AS0 0
#define O_AS1 17408
#define O_BS0 34816
#define O_BS1 43520
#define SMEM_OFF 52224

__device__ __forceinline__ void off_issue(int p, int buf, int tid, int ho,
                                          const __half* xn, u32 sbase) {
    u32 asb = sbase + (buf ? O_AS1 : O_AS0);
    u32 bsb = sbase + (buf ? O_BS1 : O_BS0);
    int ky = p / 3 - 1, kx = p % 3 - 1;
    int ih = ho + ky;
    bool vrow = (unsigned)ih < 64u;
    #pragma unroll
    for (int i = 0; i < 4; i++) {
        int c   = tid + i * 256;
        int wo  = c >> 4, c16 = c & 15;
        int iw = wo + kx;
        bool v = vrow && ((unsigned)iw < 64u);
        int iwc = v ? iw : 0;
        int ihc = vrow ? ih : 0;
        const char* src = (const char*)(xn + ((size_t)(ihc * WW + iwc)) * CIN) + c16 * 16;
        cp_async16z(asb + (u32)(wo * ROWB + c16 * 16), src, v ? 16u : 0u);
    }
    #pragma unroll
    for (int i = 0; i < 2; i++) {
        int c   = tid + i * 256;
        int row = c >> 4, c16 = c & 15;
        cp_async16(bsb + (u32)(row * ROWB + c16 * 16),
                   (const char*)(g_wo + p * 32 * CIN) + row * 256 + c16 * 16);
    }
    CP_COMMIT();
}

__global__ __launch_bounds__(256, 4)
void k_offmma(const float* __restrict__ offset_b) {
    extern __shared__ char smc[];
    u32 sbase = cvta_smem(smc);
    float* outs = (float*)smc;      // alias As0 after mainloop

    int tid  = threadIdx.x;
    int ho   = blockIdx.x;
    int n    = blockIdx.y;
    int lane = tid & 31;
    int warp = tid >> 5;
    int wm   = warp >> 1;
    int wn   = warp & 1;
    int lrow = lane & 15;
    int lcol = (lane >> 4) << 4;

    float acc[2][4];
    #pragma unroll
    for (int nt = 0; nt < 2; nt++)
        #pragma unroll
        for (int i = 0; i < 4; i++) acc[nt][i] = 0.f;

    const __half* xn = g_xh + (size_t)n * HW * CIN;

    off_issue(0, 0, tid, ho, xn, sbase);

    for (int p = 0; p < PP; p++) {
        if (p < PP - 1) {
            off_issue(p + 1, (p + 1) & 1, tid, ho, xn, sbase);
            CP_WAIT(1);
        } else {
            CP_WAIT(0);
        }
        __syncthreads();

        u32 asU = sbase + ((p & 1) ? O_AS1 : O_AS0);
        u32 bsU = sbase + ((p & 1) ? O_BS1 : O_BS0);
        #pragma unroll
        for (int ks = 0; ks < 8; ks++) {
            u32 k0b = (u32)(ks * 32 + lcol);
            u32 a[4], b[4];
            ldm4(a, asU + (u32)((wm * 16 + lrow) * ROWB) + k0b);
            ldm4(b, bsU + (u32)((wn * 16 + lrow) * ROWB) + k0b);
            mma_f16(acc[0], a, b[0], b[2]);
            mma_f16(acc[1], a, b[1], b[3]);
        }
        __syncthreads();
    }

    #pragma unroll
    for (int nt = 0; nt < 2; nt++) {
        int co = wn * 16 + nt * 8 + (lane & 3) * 2;
        int px = wm * 16 + (lane >> 2);
        #pragma unroll
        for (int h = 0; h < 2; h++) {
            int pr = px + h * 8;
            outs[pr * 33 + co]     = acc[nt][h * 2 + 0];
            outs[pr * 33 + co + 1] = acc[nt][h * 2 + 1];
        }
    }
    __syncthreads();

    for (int it = tid; it < 64 * PP; it += 256) {
        int p  = it >> 6;
        int wo = it & 63;
        float dy = outs[wo * 33 + 2 * p]     + offset_b[2 * p];
        float dx = outs[wo * 33 + 2 * p + 1] + offset_b[2 * p + 1];
        float py  = dy + (float)(p / 3) + (float)(ho - 1);
        float pxx = dx + (float)(p % 3) + (float)(wo - 1);
        float y0f = floorf(py), x0f = floorf(pxx);
        float wy = py - y0f, wx = pxx - x0f;
        int y0 = (int)y0f, x0 = (int)x0f;
        bool vy0 = (unsigned)y0       < 64u;
        bool vy1 = (unsigned)(y0 + 1) < 64u;
        bool vx0 = (unsigned)x0       < 64u;
        bool vx1 = (unsigned)(x0 + 1) < 64u;
        float w00 = (vy0 && vx0) ? (1.f - wy) * (1.f - wx) : 0.f;
        float w01 = (vy0 && vx1) ? (1.f - wy) * wx         : 0.f;
        float w10 = (vy1 && vx0) ? wy * (1.f - wx)         : 0.f;
        float w11 = (vy1 && vx1) ? wy * wx                 : 0.f;
        int y0c = min(max(y0, 0), 63),     y1c = min(max(y0 + 1, 0), 63);
        int x0c = min(max(x0, 0), 63),     x1c = min(max(x0 + 1, 0), 63);
        uint4 ma = make_uint4((u32)(y0c * (WW * CIN * 2)), (u32)(y1c * (WW * CIN * 2)),
                              (u32)(x0c * (CIN * 2)),      (u32)(x1c * (CIN * 2)));
        __half2 h00 = __float2half2_rn(w00);
        __half2 h01 = __float2half2_rn(w01);
        __half2 h10 = __float2half2_rn(w10);
        __half2 h11 = __float2half2_rn(w11);
        uint4 mw = make_uint4(*(u32*)&h00, *(u32*)&h01, *(u32*)&h10, *(u32*)&h11);
        size_t idx = ((size_t)(n * PP + p)) * PIX_PER_N + ho * WO + wo;
        g_m[2 * idx]     = ma;
        g_m[2 * idx + 1] = mw;
    }
}

// ---------------- kernel 4: gather + fp16 mma + BN + SiLU, 4 CTAs/SM ---------------
// 256 threads, tile = one ho row: 64 px x 128 co. Single As, meta cp.async x2.
// smem: As[0,17408) Bs[17408,52224) M0[52224,54272) M1[54272,56320)  total 56320
#define OFF_AS   0
#define OFF_BS   17408
#define OFF_M0   52224
#define OFF_M1   54272
#define SMEM_MAIN 56320

__device__ __forceinline__ void gather_px(int mbuf, int pix, int lane,
                                          const char* smc, const char* xb, char* smw) {
    const uint4* meta = (const uint4*)(smc + (mbuf ? OFF_M1 : OFF_M0));
    uint4 ma = meta[2 * pix];
    uint4 mw = meta[2 * pix + 1];
    int ch0 = lane * 4;
    const char* xc = xb + ch0 * 2;
    ull c00 = *(const ull*)(xc + ma.x + ma.z);
    ull c01 = *(const ull*)(xc + ma.x + ma.w);
    ull c10 = *(const ull*)(xc + ma.y + ma.z);
    ull c11 = *(const ull*)(xc + ma.y + ma.w);
    __half2 w00 = *(__half2*)&mw.x;
    __half2 w01 = *(__half2*)&mw.y;
    __half2 w10 = *(__half2*)&mw.z;
    __half2 w11 = *(__half2*)&mw.w;

    __half2 aL = __float2half2_rn(0.f), aH = aL;
    aL = __hfma2(w00, ((const __half2*)&c00)[0], aL);
    aH = __hfma2(w00, ((const __half2*)&c00)[1], aH);
    aL = __hfma2(w01, ((const __half2*)&c01)[0], aL);
    aH = __hfma2(w01, ((const __half2*)&c01)[1], aH);
    aL = __hfma2(w10, ((const __half2*)&c10)[0], aL);
    aH = __hfma2(w10, ((const __half2*)&c10)[1], aH);
    aL = __hfma2(w11, ((const __half2*)&c11)[0], aL);
    aH = __hfma2(w11, ((const __half2*)&c11)[1], aH);

    u32 lo = *(const u32*)&aL;
    u32 hi = *(const u32*)&aH;
    *(ull*)(smw + OFF_AS + pix * ROWB + ch0 * 2) = ((ull)hi << 32) | (ull)lo;
}

__device__ __forceinline__ void copy_bs(const __half* src_g, u32 dst_u, int tid) {
    const char* src = (const char*)src_g;
    #pragma unroll
    for (int i = 0; i < 8; i++) {
        int c   = tid + i * 256;
        int row = c >> 4;
        int c16 = c & 15;
        cp_async16(dst_u + (u32)(row * ROWB + c16 * 16), src + row * 256 + c16 * 16);
    }
}

__global__ __launch_bounds__(256, 4)
void k_main(const float* __restrict__ gamma,
            const float* __restrict__ beta,
            const float* __restrict__ rmean,
            const float* __restrict__ rvar,
            float* __restrict__ out) {
    extern __shared__ char smc[];
    u32 sbase = cvta_smem(smc);
    u32 bsU = sbase + OFF_BS;
    u32 mU0 = sbase + OFF_M0;
    u32 mU1 = sbase + OFF_M1;

    int tid  = threadIdx.x;
    int ho   = blockIdx.x;
    int n    = blockIdx.y;
    int lane = tid & 31;
    int warp = tid >> 5;
    int wm   = warp >> 2;
    int wn   = warp & 3;
    int gpix0 = warp * 8;

    const char* mbase0 = (const char*)(g_m + 2 * (((size_t)(n * PP)) * PIX_PER_N + ho * WO));
    const size_t mstride = (size_t)PIX_PER_N * 32;
    const char* xb = (const char*)(g_xh + (size_t)n * HW * CIN);

    // prologue: meta(0)->M0 + Bs(0); wait; gather(0); issue meta(1)->M1; wait
    if (tid < 128) cp_async16(mU0 + tid * 16, mbase0 + tid * 16);
    copy_bs(g_wf, bsU, tid);
    CP_COMMIT();
    CP_WAIT(0);
    __syncthreads();
    #pragma unroll 4
    for (int pl = 0; pl < 8; pl++)
        gather_px(0, gpix0 + pl, lane, smc, xb, smc);
    if (tid < 128) cp_async16(mU1 + tid * 16, mbase0 + mstride + tid * 16);
    CP_COMMIT();
    CP_WAIT(0);
    __syncthreads();

    float acc[2][4][4];
    #pragma unroll
    for (int mt = 0; mt < 2; mt++)
        #pragma unroll
        for (int nt = 0; nt < 4; nt++)
            #pragma unroll
            for (int i = 0; i < 4; i++) acc[mt][nt][i] = 0.f;

    int lrow = lane & 15;
    int lcol = (lane >> 4) << 4;

    for (int p = 0; p < PP; p++) {
        // ---- GEMM tap p ----
        #pragma unroll
        for (int ks = 0; ks < 8; ks++) {
            u32 k0b = (u32)(ks * 32 + lcol);
            u32 a[2][4], b[2][4];
            #pragma unroll
            for (int mt = 0; mt < 2; mt++)
                ldm4(a[mt], sbase + OFF_AS + (u32)((wm * 32 + mt * 16 + lrow) * ROWB) + k0b);
            #pragma unroll
            for (int pr = 0; pr < 2; pr++)
                ldm4(b[pr], bsU + (u32)((wn * 32 + pr * 16 + lrow) * ROWB) + k0b);
            #pragma unroll
            for (int mt = 0; mt < 2; mt++)
                #pragma unroll
                for (int nt = 0; nt < 4; nt++) {
                    int pr = nt >> 1, s = nt & 1;
                    mma_f16(acc[mt][nt], a[mt], b[pr][s], b[pr][2 + s]);
                }
        }
        __syncthreads();                 // done reading As/Bs tap p
        if (p < PP - 1) {
            copy_bs(g_wf + (size_t)(p + 1) * COUT * CIN, bsU, tid);
            if (p + 2 < PP && tid < 128)
                cp_async16((((p & 1) == 0) ? mU0 : mU1) + tid * 16,
                           mbase0 + (size_t)(p + 2) * mstride + tid * 16);
            CP_COMMIT();
            // gather(p+1) from meta buf (p+1)&1 — landed in previous iteration
            #pragma unroll 4
            for (int pl = 0; pl < 8; pl++)
                gather_px((p + 1) & 1, gpix0 + pl, lane, smc, xb, smc);
            CP_WAIT(0);
            __syncthreads();
        }
    }

    // ---- epilogue: BN + SiLU (BN params direct from gmem; L2-hit broadcasts) ----
    #pragma unroll
    for (int mt = 0; mt < 2; mt++)
        #pragma unroll
        for (int nt = 0; nt < 4; nt++) {
            int co = wn * 32 + nt * 8 + (lane & 3) * 2;
            int px = wm * 32 + mt * 16 + (lane >> 2);
            float s0 = gamma[co]     * rsqrtf(rvar[co]     + 1e-5f);
            float s1 = gamma[co + 1] * rsqrtf(rvar[co + 1] + 1e-5f);
            float b0 = beta[co]     - rmean[co]     * s0;
            float b1 = beta[co + 1] - rmean[co + 1] * s1;
            #pragma unroll
            for (int h = 0; h < 2; h++) {
                int wo = px + h * 8;
                float y0v = acc[mt][nt][h * 2 + 0] * s0 + b0;
                float y1v = acc[mt][nt][h * 2 + 1] * s1 + b1;
                out[(((size_t)(n * COUT + co))     * HO + ho) * WO + wo] = y0v / (1.f + __expf(-y0v));
                out[(((size_t)(n * COUT + co + 1)) * HO + ho) * WO + wo] = y1v / (1.f + __expf(-y1v));
            }
        }
}

// ---------------- launch ----------------
extern "C" void kernel_launch(void* const* d_in, const int* in_sizes, int n_in,
                              void* d_out, int out_size) {
    const float* x        = (const float*)d_in[0];
    const float* offset_w = (const float*)d_in[1];
    const float* offset_b = (const float*)d_in[2];
    const float* deform_w = (const float*)d_in[3];
    const float* gamma    = (const float*)d_in[4];
    const float* beta     = (const float*)d_in[5];
    const float* rmean    = (const float*)d_in[6];
    const float* rvar     = (const float*)d_in[7];
    float* out = (float*)d_out;

    cudaFuncSetAttribute(k_offmma, cudaFuncAttributeMaxDynamicSharedMemorySize, SMEM_OFF);
    cudaFuncSetAttribute(k_main,   cudaFuncAttributeMaxDynamicSharedMemorySize, SMEM_MAIN);

    k_transpose_x<<<dim3(HW / 64, CIN / 32, NB), 256>>>(x);
    k_prep<<<(PP * COUT * CIN + PP * 32 * CIN + 255) / 256, 256>>>(deform_w, offset_w);

    k_offmma<<<dim3(HO, NB), 256, SMEM_OFF>>>(offset_b);

    k_main<<<dim3(HO, NB), 256, SMEM_MAIN>>>(gamma, beta, rmean, rvar, out);
}

// round 16
// speedup vs baseline: 1.2590x; 1.0448x over previous
#include <cuda_runtime.h>
#include <cuda_bf16.h>
#include <cuda_fp16.h>
#include <math.h>

typedef unsigned long long ull;
typedef unsigned int u32;

// Problem constants
#define NB   16
#define CIN  128
#define COUT 128
#define HH   64
#define WW   64
#define HO   64
#define WO   64
#define PP   9
#define HW   (HH*WW)
#define PIX_PER_N (HO*WO)

#define ROWB 272   // smem row stride (136 f16 = 17*16B, conflict-free ldmatrix)

// ---------------- scratch ----------------
__device__ __align__(16) __half g_xh[NB * HH * WW * CIN];   // NHWC x, fp16
__device__ __align__(16) __half g_wf[PP * COUT * CIN];      // [p][cout][cin] fp16 (deform)
__device__ __align__(16) __half g_wo[PP * 32 * CIN];        // [p][cout_pad32][cin] fp16 (offset)
__device__ uint4 g_m[NB * PP * PIX_PER_N * 2];              // per idx: {ma, mw} interleaved

// ---------------- helpers ----------------
__device__ __forceinline__ u32 cvta_smem(const void* p) {
    u32 r;
    asm("{ .reg .u64 t; cvta.to.shared.u64 t, %1; cvt.u32.u64 %0, t; }" : "=r"(r) : "l"(p));
    return r;
}
__device__ __forceinline__ void ldm4(u32* r, u32 addr) {
    asm volatile("ldmatrix.sync.aligned.m8n8.x4.shared.b16 {%0,%1,%2,%3}, [%4];"
                 : "=r"(r[0]), "=r"(r[1]), "=r"(r[2]), "=r"(r[3]) : "r"(addr));
}
__device__ __forceinline__ void mma_f16(float* c, const u32* a, u32 b0, u32 b1) {
    asm volatile("mma.sync.aligned.m16n8k16.row.col.f32.f16.f16.f32 "
                 "{%0,%1,%2,%3}, {%4,%5,%6,%7}, {%8,%9}, {%0,%1,%2,%3};"
                 : "+f"(c[0]), "+f"(c[1]), "+f"(c[2]), "+f"(c[3])
                 : "r"(a[0]), "r"(a[1]), "r"(a[2]), "r"(a[3]), "r"(b0), "r"(b1));
}
__device__ __forceinline__ void cp_async16(u32 dst, const void* src) {
    asm volatile("cp.async.cg.shared.global [%0], [%1], 16;" :: "r"(dst), "l"(src));
}
__device__ __forceinline__ void cp_async16z(u32 dst, const void* src, u32 srcsz) {
    asm volatile("cp.async.cg.shared.global [%0], [%1], 16, %2;" :: "r"(dst), "l"(src), "r"(srcsz));
}
#define CP_COMMIT()  asm volatile("cp.async.commit_group;" ::: "memory")
#define CP_WAIT(n)   asm volatile("cp.async.wait_group %0;" :: "n"(n) : "memory")

// ---------------- kernel 1: x NCHW fp32 -> NHWC fp16 (vectorized) ----------------
__global__ void k_transpose_x(const float* __restrict__ x) {
    __shared__ float tile[32][67];
    int n   = blockIdx.z;
    int hw0 = blockIdx.x * 64;
    int c0  = blockIdx.y * 32;
    int tid = threadIdx.x;
    #pragma unroll
    for (int i = 0; i < 2; i++) {
        int idx  = tid + i * 256;
        int row  = idx >> 4;
        int col4 = idx & 15;
        const float4* src = (const float4*)(x + ((size_t)(n * CIN + c0 + row)) * HW + hw0);
        float4 v = src[col4];
        tile[row][col4 * 4 + 0] = v.x;
        tile[row][col4 * 4 + 1] = v.y;
        tile[row][col4 * 4 + 2] = v.z;
        tile[row][col4 * 4 + 3] = v.w;
    }
    __syncthreads();
    #pragma unroll
    for (int i = 0; i < 4; i++) {
        int idx = tid + i * 256;
        int hw  = idx >> 4;
        int cp  = idx & 15;
        __half2 h = __halves2half2(__float2half_rn(tile[2 * cp][hw]),
                                   __float2half_rn(tile[2 * cp + 1][hw]));
        *(__half2*)&g_xh[((size_t)(n * HW + hw0 + hw)) * CIN + c0 + 2 * cp] = h;
    }
}

// ---------------- kernel 2: merged weight prep ----------------
__global__ void k_prep(const float* __restrict__ wf_src, const float* __restrict__ wo_src) {
    int i = blockIdx.x * 256 + threadIdx.x;
    if (i < PP * COUT * CIN) {
        int cin  = i & 127;
        int cout = (i >> 7) & 127;
        int p    = i >> 14;
        g_wf[i] = __float2half_rn(wf_src[(cout * CIN + cin) * PP + p]);
    } else {
        int j = i - PP * COUT * CIN;
        if (j < PP * 32 * CIN) {
            int cin  = j & 127;
            int cout = (j >> 7) & 31;
            int p    = j >> 12;
            g_wo[j] = (cout < 18) ? __float2half_rn(wo_src[(cout * CIN + cin) * PP + p])
                                  : __ushort_as_half((unsigned short)0);
        }
    }
}

// ---------------- kernel 3: offset conv via fp16 mma (64px, 4 CTA/SM, pipelined) ---
#define O_AS0 0
#define O_AS1 17408
#define O_BS0 34816
#define O_BS1 43520
#define SMEM_OFF 52224

__device__ __forceinline__ void off_issue(int p, int buf, int tid, int ho,
                                          const __half* xn, u32 sbase) {
    u32 asb = sbase + (buf ? O_AS1 : O_AS0);
    u32 bsb = sbase + (buf ? O_BS1 : O_BS0);
    int ky = p / 3 - 1, kx = p % 3 - 1;
    int ih = ho + ky;
    bool vrow = (unsigned)ih < 64u;
    #pragma unroll
    for (int i = 0; i < 4; i++) {
        int c   = tid + i * 256;
        int wo  = c >> 4, c16 = c & 15;
        int iw = wo + kx;
        bool v = vrow && ((unsigned)iw < 64u);
        int iwc = v ? iw : 0;
        int ihc = vrow ? ih : 0;
        const char* src = (const char*)(xn + ((size_t)(ihc * WW + iwc)) * CIN) + c16 * 16;
        cp_async16z(asb + (u32)(wo * ROWB + c16 * 16), src, v ? 16u : 0u);
    }
    #pragma unroll
    for (int i = 0; i < 2; i++) {
        int c   = tid + i * 256;
        int row = c >> 4, c16 = c & 15;
        cp_async16(bsb + (u32)(row * ROWB + c16 * 16),
                   (const char*)(g_wo + p * 32 * CIN) + row * 256 + c16 * 16);
    }
    CP_COMMIT();
}

__global__ __launch_bounds__(256, 4)
void k_offmma(const float* __restrict__ offset_b) {
    extern __shared__ char smc[];
    u32 sbase = cvta_smem(smc);
    float* outs = (float*)smc;      // alias As0 after mainloop

    int tid  = threadIdx.x;
    int ho   = blockIdx.x;
    int n    = blockIdx.y;
    int lane = tid & 31;
    int warp = tid >> 5;
    int wm   = warp >> 1;
    int wn   = warp & 1;
    int lrow = lane & 15;
    int lcol = (lane >> 4) << 4;

    float acc[2][4];
    #pragma unroll
    for (int nt = 0; nt < 2; nt++)
        #pragma unroll
        for (int i = 0; i < 4; i++) acc[nt][i] = 0.f;

    const __half* xn = g_xh + (size_t)n * HW * CIN;

    off_issue(0, 0, tid, ho, xn, sbase);

    for (int p = 0; p < PP; p++) {
        if (p < PP - 1) {
            off_issue(p + 1, (p + 1) & 1, tid, ho, xn, sbase);
            CP_WAIT(1);
        } else {
            CP_WAIT(0);
        }
        __syncthreads();

        u32 asU = sbase + ((p & 1) ? O_AS1 : O_AS0);
        u32 bsU = sbase + ((p & 1) ? O_BS1 : O_BS0);
        #pragma unroll
        for (int ks = 0; ks < 8; ks++) {
            u32 k0b = (u32)(ks * 32 + lcol);
            u32 a[4], b[4];
            ldm4(a, asU + (u32)((wm * 16 + lrow) * ROWB) + k0b);
            ldm4(b, bsU + (u32)((wn * 16 + lrow) * ROWB) + k0b);
            mma_f16(acc[0], a, b[0], b[2]);
            mma_f16(acc[1], a, b[1], b[3]);
        }
        __syncthreads();
    }

    #pragma unroll
    for (int nt = 0; nt < 2; nt++) {
        int co = wn * 16 + nt * 8 + (lane & 3) * 2;
        int px = wm * 16 + (lane >> 2);
        #pragma unroll
        for (int h = 0; h < 2; h++) {
            int pr = px + h * 8;
            outs[pr * 33 + co]     = acc[nt][h * 2 + 0];
            outs[pr * 33 + co + 1] = acc[nt][h * 2 + 1];
        }
    }
    __syncthreads();

    for (int it = tid; it < 64 * PP; it += 256) {
        int p  = it >> 6;
        int wo = it & 63;
        float dy = outs[wo * 33 + 2 * p]     + offset_b[2 * p];
        float dx = outs[wo * 33 + 2 * p + 1] + offset_b[2 * p + 1];
        float py  = dy + (float)(p / 3) + (float)(ho - 1);
        float pxx = dx + (float)(p % 3) + (float)(wo - 1);
        float y0f = floorf(py), x0f = floorf(pxx);
        float wy = py - y0f, wx = pxx - x0f;
        int y0 = (int)y0f, x0 = (int)x0f;
        bool vy0 = (unsigned)y0       < 64u;
        bool vy1 = (unsigned)(y0 + 1) < 64u;
        bool vx0 = (unsigned)x0       < 64u;
        bool vx1 = (unsigned)(x0 + 1) < 64u;
        float w00 = (vy0 && vx0) ? (1.f - wy) * (1.f - wx) : 0.f;
        float w01 = (vy0 && vx1) ? (1.f - wy) * wx         : 0.f;
        float w10 = (vy1 && vx0) ? wy * (1.f - wx)         : 0.f;
        float w11 = (vy1 && vx1) ? wy * wx                 : 0.f;
        int y0c = min(max(y0, 0), 63),     y1c = min(max(y0 + 1, 0), 63);
        int x0c = min(max(x0, 0), 63),     x1c = min(max(x0 + 1, 0), 63);
        uint4 ma = make_uint4((u32)(y0c * (WW * CIN * 2)), (u32)(y1c * (WW * CIN * 2)),
                              (u32)(x0c * (CIN * 2)),      (u32)(x1c * (CIN * 2)));
        __half2 h00 = __float2half2_rn(w00);
        __half2 h01 = __float2half2_rn(w01);
        __half2 h10 = __float2half2_rn(w10);
        __half2 h11 = __float2half2_rn(w11);
        uint4 mw = make_uint4(*(u32*)&h00, *(u32*)&h01, *(u32*)&h10, *(u32*)&h11);
        size_t idx = ((size_t)(n * PP + p)) * PIX_PER_N + ho * WO + wo;
        g_m[2 * idx]     = ma;
        g_m[2 * idx + 1] = mw;
    }
}

// ---------------- kernel 4: gather + fp16 mma + BN + SiLU, 4 CTAs/SM ---------------
// 256 threads, tile = one ho row: 64 px x 128 co. Single As, meta cp.async x2.
// smem: As[0,17408) Bs[17408,52224) M0[52224,54272) M1[54272,56320)  total 56320
#define OFF_AS   0
#define OFF_BS   17408
#define OFF_M0   52224
#define OFF_M1   54272
#define SMEM_MAIN 56320

// half-warp-wide gather: 16 lanes per pixel, 8 channels per lane, 2 px per iteration
__device__ __forceinline__ void gather_pair(int mbuf, int i, int gpix0, int lane,
                                            const char* smc, const char* xb, char* smw) {
    const uint4* meta = (const uint4*)(smc + (mbuf ? OFF_M1 : OFF_M0));
    int pix = gpix0 + 2 * i + (lane >> 4);
    int chb = (lane & 15) * 16;              // byte offset of 8-channel group
    uint4 ma = meta[2 * pix];
    uint4 mw = meta[2 * pix + 1];
    const char* xc = xb + chb;
    __half2 w00 = *(__half2*)&mw.x;
    __half2 w01 = *(__half2*)&mw.y;
    __half2 w10 = *(__half2*)&mw.z;
    __half2 w11 = *(__half2*)&mw.w;

    __half2 z = __float2half2_rn(0.f);
    __half2 r0 = z, r1 = z, r2 = z, r3 = z;
    {
        uint4 cA = *(const uint4*)(xc + ma.x + ma.z);
        uint4 cB = *(const uint4*)(xc + ma.x + ma.w);
        r0 = __hfma2(w00, ((const __half2*)&cA)[0], r0);
        r1 = __hfma2(w00, ((const __half2*)&cA)[1], r1);
        r2 = __hfma2(w00, ((const __half2*)&cA)[2], r2);
        r3 = __hfma2(w00, ((const __half2*)&cA)[3], r3);
        r0 = __hfma2(w01, ((const __half2*)&cB)[0], r0);
        r1 = __hfma2(w01, ((const __half2*)&cB)[1], r1);
        r2 = __hfma2(w01, ((const __half2*)&cB)[2], r2);
        r3 = __hfma2(w01, ((const __half2*)&cB)[3], r3);
    }
    {
        uint4 cA = *(const uint4*)(xc + ma.y + ma.z);
        uint4 cB = *(const uint4*)(xc + ma.y + ma.w);
        r0 = __hfma2(w10, ((const __half2*)&cA)[0], r0);
        r1 = __hfma2(w10, ((const __half2*)&cA)[1], r1);
        r2 = __hfma2(w10, ((const __half2*)&cA)[2], r2);
        r3 = __hfma2(w10, ((const __half2*)&cA)[3], r3);
        r0 = __hfma2(w11, ((const __half2*)&cB)[0], r0);
        r1 = __hfma2(w11, ((const __half2*)&cB)[1], r1);
        r2 = __hfma2(w11, ((const __half2*)&cB)[2], r2);
        r3 = __hfma2(w11, ((const __half2*)&cB)[3], r3);
    }
    uint4 o;
    o.x = *(const u32*)&r0;
    o.y = *(const u32*)&r1;
    o.z = *(const u32*)&r2;
    o.w = *(const u32*)&r3;
    *(uint4*)(smw + OFF_AS + pix * ROWB + chb) = o;
}

__device__ __forceinline__ void copy_bs(const __half* src_g, u32 dst_u, int tid) {
    const char* src = (const char*)src_g;
    #pragma unroll
    for (int i = 0; i < 8; i++) {
        int c   = tid + i * 256;
        int row = c >> 4;
        int c16 = c & 15;
        cp_async16(dst_u + (u32)(row * ROWB + c16 * 16), src + row * 256 + c16 * 16);
    }
}

__global__ __launch_bounds__(256, 4)
void k_main(const float* __restrict__ gamma,
            const float* __restrict__ beta,
            const float* __restrict__ rmean,
            const float* __restrict__ rvar,
            float* __restrict__ out) {
    extern __shared__ char smc[];
    u32 sbase = cvta_smem(smc);
    u32 bsU = sbase + OFF_BS;
    u32 mU0 = sbase + OFF_M0;
    u32 mU1 = sbase + OFF_M1;

    int tid  = threadIdx.x;
    int ho   = blockIdx.x;
    int n    = blockIdx.y;
    int lane = tid & 31;
    int warp = tid >> 5;
    int wm   = warp >> 2;
    int wn   = warp & 3;
    int gpix0 = warp * 8;

    const char* mbase0 = (const char*)(g_m + 2 * (((size_t)(n * PP)) * PIX_PER_N + ho * WO));
    const size_t mstride = (size_t)PIX_PER_N * 32;
    const char* xb = (const char*)(g_xh + (size_t)n * HW * CIN);

    // prologue: meta(0)->M0 + Bs(0); wait; gather(0); issue meta(1)->M1; wait
    if (tid < 128) cp_async16(mU0 + tid * 16, mbase0 + tid * 16);
    copy_bs(g_wf, bsU, tid);
    CP_COMMIT();
    CP_WAIT(0);
    __syncthreads();
    #pragma unroll
    for (int i = 0; i < 4; i++)
        gather_pair(0, i, gpix0, lane, smc, xb, smc);
    if (tid < 128) cp_async16(mU1 + tid * 16, mbase0 + mstride + tid * 16);
    CP_COMMIT();
    CP_WAIT(0);
    __syncthreads();

    float acc[2][4][4];
    #pragma unroll
    for (int mt = 0; mt < 2; mt++)
        #pragma unroll
        for (int nt = 0; nt < 4; nt++)
            #pragma unroll
            for (int i = 0; i < 4; i++) acc[mt][nt][i] = 0.f;

    int lrow = lane & 15;
    int lcol = (lane >> 4) << 4;
    // hoisted ldmatrix bases
    u32 aB0 = sbase + OFF_AS + (u32)((wm * 32 + lrow) * ROWB) + (u32)lcol;
    u32 aB1 = aB0 + 16u * ROWB;
    u32 bB0 = bsU + (u32)((wn * 32 + lrow) * ROWB) + (u32)lcol;
    u32 bB1 = bB0 + 16u * ROWB;

    for (int p = 0; p < PP; p++) {
        // ---- GEMM tap p ----
        #pragma unroll
        for (int ks = 0; ks < 8; ks++) {
            u32 kb = (u32)(ks * 32);
            u32 a[2][4], b[2][4];
            ldm4(a[0], aB0 + kb);
            ldm4(a[1], aB1 + kb);
            ldm4(b[0], bB0 + kb);
            ldm4(b[1], bB1 + kb);
            #pragma unroll
            for (int mt = 0; mt < 2; mt++)
                #pragma unroll
                for (int nt = 0; nt < 4; nt++) {
                    int pr = nt >> 1, s = nt & 1;
                    mma_f16(acc[mt][nt], a[mt], b[pr][s], b[pr][2 + s]);
                }
        }
        __syncthreads();                 // done reading As/Bs tap p
        if (p < PP - 1) {
            copy_bs(g_wf + (size_t)(p + 1) * COUT * CIN, bsU, tid);
            if (p + 2 < PP && tid < 128)
                cp_async16((((p & 1) == 0) ? mU0 : mU1) + tid * 16,
                           mbase0 + (size_t)(p + 2) * mstride + tid * 16);
            CP_COMMIT();
            // gather(p+1) from meta buf (p+1)&1 — landed in previous iteration
            #pragma unroll
            for (int i = 0; i < 4; i++)
                gather_pair((p + 1) & 1, i, gpix0, lane, smc, xb, smc);
            CP_WAIT(0);
            __syncthreads();
        }
    }

    // ---- epilogue: BN + SiLU (BN params direct from gmem; L2-hit broadcasts) ----
    #pragma unroll
    for (int mt = 0; mt < 2; mt++)
        #pragma unroll
        for (int nt = 0; nt < 4; nt++) {
            int co = wn * 32 + nt * 8 + (lane & 3) * 2;
            int px = wm * 32 + mt * 16 + (lane >> 2);
            float s0 = gamma[co]     * rsqrtf(rvar[co]     + 1e-5f);
            float s1 = gamma[co + 1] * rsqrtf(rvar[co + 1] + 1e-5f);
            float b0 = beta[co]     - rmean[co]     * s0;
            float b1 = beta[co + 1] - rmean[co + 1] * s1;
            #pragma unroll
            for (int h = 0; h < 2; h++) {
                int wo = px + h * 8;
                float y0v = acc[mt][nt][h * 2 + 0] * s0 + b0;
                float y1v = acc[mt][nt][h * 2 + 1] * s1 + b1;
                out[(((size_t)(n * COUT + co))     * HO + ho) * WO + wo] = y0v / (1.f + __expf(-y0v));
                out[(((size_t)(n * COUT + co + 1)) * HO + ho) * WO + wo] = y1v / (1.f + __expf(-y1v));
            }
        }
}

// ---------------- launch ----------------
extern "C" void kernel_launch(void* const* d_in, const int* in_sizes, int n_in,
                              void* d_out, int out_size) {
    const float* x        = (const float*)d_in[0];
    const float* offset_w = (const float*)d_in[1];
    const float* offset_b = (const float*)d_in[2];
    const float* deform_w = (const float*)d_in[3];
    const float* gamma    = (const float*)d_in[4];
    const float* beta     = (const float*)d_in[5];
    const float* rmean    = (const float*)d_in[6];
    const float* rvar     = (const float*)d_in[7];
    float* out = (float*)d_out;

    cudaFuncSetAttribute(k_offmma, cudaFuncAttributeMaxDynamicSharedMemorySize, SMEM_OFF);
    cudaFuncSetAttribute(k_main,   cudaFuncAttributeMaxDynamicSharedMemorySize, SMEM_MAIN);

    k_transpose_x<<<dim3(HW / 64, CIN / 32, NB), 256>>>(x);
    k_prep<<<(PP * COUT * CIN + PP * 32 * CIN + 255) / 256, 256>>>(deform_w, offset_w);

    k_offmma<<<dim3(HO, NB), 256, SMEM_OFF>>>(offset_b);

    k_main<<<dim3(HO, NB), 256, SMEM_MAIN>>>(gamma, beta, rmean, rvar, out);
}

// round 17
// speedup vs baseline: 1.2971x; 1.0303x over previous
#include <cuda_runtime.h>
#include <cuda_bf16.h>
#include <cuda_fp16.h>
#include <math.h>

typedef unsigned long long ull;
typedef unsigned int u32;

// Problem constants
#define NB   16
#define CIN  128
#define COUT 128
#define HH   64
#define WW   64
#define HO   64
#define WO   64
#define PP   9
#define HW   (HH*WW)
#define PIX_PER_N (HO*WO)

#define ROWB 272   // smem row stride (136 f16 = 17*16B, conflict-free ldmatrix)

// ---------------- scratch ----------------
__device__ __align__(16) __half g_xh[NB * HH * WW * CIN];   // NHWC x, fp16
__device__ __align__(16) __half g_wf[PP * COUT * CIN];      // [p][cout][cin] fp16 (deform)
__device__ __align__(16) __half g_wo[PP * 32 * CIN];        // [p][cout_pad32][cin] fp16 (offset)
__device__ uint4 g_m[NB * PP * PIX_PER_N * 2];              // per idx: {ma, mw} interleaved

// ---------------- helpers ----------------
__device__ __forceinline__ u32 cvta_smem(const void* p) {
    u32 r;
    asm("{ .reg .u64 t; cvta.to.shared.u64 t, %1; cvt.u32.u64 %0, t; }" : "=r"(r) : "l"(p));
    return r;
}
__device__ __forceinline__ void ldm4(u32* r, u32 addr) {
    asm volatile("ldmatrix.sync.aligned.m8n8.x4.shared.b16 {%0,%1,%2,%3}, [%4];"
                 : "=r"(r[0]), "=r"(r[1]), "=r"(r[2]), "=r"(r[3]) : "r"(addr));
}
__device__ __forceinline__ void mma_f16(float* c, const u32* a, u32 b0, u32 b1) {
    asm volatile("mma.sync.aligned.m16n8k16.row.col.f32.f16.f16.f32 "
                 "{%0,%1,%2,%3}, {%4,%5,%6,%7}, {%8,%9}, {%0,%1,%2,%3};"
                 : "+f"(c[0]), "+f"(c[1]), "+f"(c[2]), "+f"(c[3])
                 : "r"(a[0]), "r"(a[1]), "r"(a[2]), "r"(a[3]), "r"(b0), "r"(b1));
}
__device__ __forceinline__ void cp_async16(u32 dst, const void* src) {
    asm volatile("cp.async.cg.shared.global [%0], [%1], 16;" :: "r"(dst), "l"(src));
}
__device__ __forceinline__ void cp_async16z(u32 dst, const void* src, u32 srcsz) {
    asm volatile("cp.async.cg.shared.global [%0], [%1], 16, %2;" :: "r"(dst), "l"(src), "r"(srcsz));
}
#define CP_COMMIT()  asm volatile("cp.async.commit_group;" ::: "memory")
#define CP_WAIT(n)   asm volatile("cp.async.wait_group %0;" :: "n"(n) : "memory")

// ---------------- kernel 1: x NCHW fp32 -> NHWC fp16 (vectorized) ----------------
__global__ void k_transpose_x(const float* __restrict__ x) {
    __shared__ float tile[32][67];
    int n   = blockIdx.z;
    int hw0 = blockIdx.x * 64;
    int c0  = blockIdx.y * 32;
    int tid = threadIdx.x;
    #pragma unroll
    for (int i = 0; i < 2; i++) {
        int idx  = tid + i * 256;
        int row  = idx >> 4;
        int col4 = idx & 15;
        const float4* src = (const float4*)(x + ((size_t)(n * CIN + c0 + row)) * HW + hw0);
        float4 v = src[col4];
        tile[row][col4 * 4 + 0] = v.x;
        tile[row][col4 * 4 + 1] = v.y;
        tile[row][col4 * 4 + 2] = v.z;
        tile[row][col4 * 4 + 3] = v.w;
    }
    __syncthreads();
    #pragma unroll
    for (int i = 0; i < 4; i++) {
        int idx = tid + i * 256;
        int hw  = idx >> 4;
        int cp  = idx & 15;
        __half2 h = __halves2half2(__float2half_rn(tile[2 * cp][hw]),
                                   __float2half_rn(tile[2 * cp + 1][hw]));
        *(__half2*)&g_xh[((size_t)(n * HW + hw0 + hw)) * CIN + c0 + 2 * cp] = h;
    }
}

// ---------------- kernel 2: merged weight prep ----------------
__global__ void k_prep(const float* __restrict__ wf_src, const float* __restrict__ wo_src) {
    int i = blockIdx.x * 256 + threadIdx.x;
    if (i < PP * COUT * CIN) {
        int cin  = i & 127;
        int cout = (i >> 7) & 127;
        int p    = i >> 14;
        g_wf[i] = __float2half_rn(wf_src[(cout * CIN + cin) * PP + p]);
    } else {
        int j = i - PP * COUT * CIN;
        if (j < PP * 32 * CIN) {
            int cin  = j & 127;
            int cout = (j >> 7) & 31;
            int p    = j >> 12;
            g_wo[j] = (cout < 18) ? __float2half_rn(wo_src[(cout * CIN + cin) * PP + p])
                                  : __ushort_as_half((unsigned short)0);
        }
    }
}

// ---------------- kernel 3: offset conv via fp16 mma — halo As, load once ----------
// As halo: 3 input rows x 66 px (iw -1..64), 198 rows x 272B = 53856 B, loaded ONCE.
// Tap (ky,kx) reads 64 rows starting at (ky*66 + kx). Bs double-buffered 8704B each.
// outs (64*33 floats = 8448B) aliases As after mainloop.
#define OH_AS  0
#define OH_BS0 53856
#define OH_BS1 62560
#define SMEM_OFF 71264

__global__ __launch_bounds__(256, 3)
void k_offmma(const float* __restrict__ offset_b) {
    extern __shared__ char smc[];
    u32 sbase = cvta_smem(smc);
    float* outs = (float*)smc;      // alias As after mainloop

    int tid  = threadIdx.x;
    int ho   = blockIdx.x;
    int n    = blockIdx.y;
    int lane = tid & 31;
    int warp = tid >> 5;
    int wm   = warp >> 1;      // 0..3 (16-px groups)
    int wn   = warp & 1;       // 0..1 (16-co groups)
    int lrow = lane & 15;
    int lcol = (lane >> 4) << 4;

    float acc[2][4];
    #pragma unroll
    for (int nt = 0; nt < 2; nt++)
        #pragma unroll
        for (int i = 0; i < 4; i++) acc[nt][i] = 0.f;

    const __half* xn = g_xh + (size_t)n * HW * CIN;

    // ---- prologue: halo As (group 0) + Bs(0) (group 1) ----
    #pragma unroll
    for (int i = 0; i < 13; i++) {
        int c = tid + i * 256;
        if (c < 198 * 16) {
            int row = c >> 4, c16 = c & 15;
            int r   = row / 66;            // 0..2
            int pxl = row - r * 66;        // 0..65
            int ih  = ho - 1 + r;
            int iw  = pxl - 1;
            bool v = ((unsigned)ih < 64u) && ((unsigned)iw < 64u);
            int ihc = v ? ih : 0, iwc = v ? iw : 0;
            const char* src = (const char*)(xn + ((size_t)(ihc * WW + iwc)) * CIN) + c16 * 16;
            cp_async16z(sbase + OH_AS + (u32)(row * ROWB + c16 * 16), src, v ? 16u : 0u);
        }
    }
    CP_COMMIT();
    #pragma unroll
    for (int i = 0; i < 2; i++) {
        int c   = tid + i * 256;
        int row = c >> 4, c16 = c & 15;
        cp_async16(sbase + OH_BS0 + (u32)(row * ROWB + c16 * 16),
                   (const char*)g_wo + row * 256 + c16 * 16);
    }
    CP_COMMIT();

    for (int p = 0; p < PP; p++) {
        if (p < PP - 1) {
            // issue Bs(p+1) into buf (p+1)&1 — safe: last reader synced below
            u32 bsn = sbase + (((p + 1) & 1) ? OH_BS1 : OH_BS0);
            #pragma unroll
            for (int i = 0; i < 2; i++) {
                int c   = tid + i * 256;
                int row = c >> 4, c16 = c & 15;
                cp_async16(bsn + (u32)(row * ROWB + c16 * 16),
                           (const char*)(g_wo + (p + 1) * 32 * CIN) + row * 256 + c16 * 16);
            }
            CP_COMMIT();
            CP_WAIT(1);
        } else {
            CP_WAIT(0);
        }
        __syncthreads();

        int ky = p / 3, kx = p % 3;
        u32 aBase = sbase + OH_AS + (u32)((ky * 66 + kx) * ROWB);
        u32 bsU   = sbase + ((p & 1) ? OH_BS1 : OH_BS0);
        u32 aRow  = aBase + (u32)((wm * 16 + lrow) * ROWB) + (u32)lcol;
        u32 bRow  = bsU + (u32)((wn * 16 + lrow) * ROWB) + (u32)lcol;
        #pragma unroll
        for (int ks = 0; ks < 8; ks++) {
            u32 kb = (u32)(ks * 32);
            u32 a[4], b[4];
            ldm4(a, aRow + kb);
            ldm4(b, bRow + kb);
            mma_f16(acc[0], a, b[0], b[2]);
            mma_f16(acc[1], a, b[1], b[3]);
        }
        __syncthreads();
    }

    // write acc -> outs[wo][co] (stride 33), outs aliases As (safe post-sync)
    #pragma unroll
    for (int nt = 0; nt < 2; nt++) {
        int co = wn * 16 + nt * 8 + (lane & 3) * 2;
        int px = wm * 16 + (lane >> 2);
        #pragma unroll
        for (int h = 0; h < 2; h++) {
            int pr = px + h * 8;
            outs[pr * 33 + co]     = acc[nt][h * 2 + 0];
            outs[pr * 33 + co + 1] = acc[nt][h * 2 + 1];
        }
    }
    __syncthreads();

    // metadata: clamped byte offsets + validity-folded half2 weights
    for (int it = tid; it < 64 * PP; it += 256) {
        int p  = it >> 6;
        int wo = it & 63;
        float dy = outs[wo * 33 + 2 * p]     + offset_b[2 * p];
        float dx = outs[wo * 33 + 2 * p + 1] + offset_b[2 * p + 1];
        float py  = dy + (float)(p / 3) + (float)(ho - 1);
        float pxx = dx + (float)(p % 3) + (float)(wo - 1);
        float y0f = floorf(py), x0f = floorf(pxx);
        float wy = py - y0f, wx = pxx - x0f;
        int y0 = (int)y0f, x0 = (int)x0f;
        bool vy0 = (unsigned)y0       < 64u;
        bool vy1 = (unsigned)(y0 + 1) < 64u;
        bool vx0 = (unsigned)x0       < 64u;
        bool vx1 = (unsigned)(x0 + 1) < 64u;
        float w00 = (vy0 && vx0) ? (1.f - wy) * (1.f - wx) : 0.f;
        float w01 = (vy0 && vx1) ? (1.f - wy) * wx         : 0.f;
        float w10 = (vy1 && vx0) ? wy * (1.f - wx)         : 0.f;
        float w11 = (vy1 && vx1) ? wy * wx                 : 0.f;
        int y0c = min(max(y0, 0), 63),     y1c = min(max(y0 + 1, 0), 63);
        int x0c = min(max(x0, 0), 63),     x1c = min(max(x0 + 1, 0), 63);
        uint4 ma = make_uint4((u32)(y0c * (WW * CIN * 2)), (u32)(y1c * (WW * CIN * 2)),
                              (u32)(x0c * (CIN * 2)),      (u32)(x1c * (CIN * 2)));
        __half2 h00 = __float2half2_rn(w00);
        __half2 h01 = __float2half2_rn(w01);
        __half2 h10 = __float2half2_rn(w10);
        __half2 h11 = __float2half2_rn(w11);
        uint4 mw = make_uint4(*(u32*)&h00, *(u32*)&h01, *(u32*)&h10, *(u32*)&h11);
        size_t idx = ((size_t)(n * PP + p)) * PIX_PER_N + ho * WO + wo;
        g_m[2 * idx]     = ma;
        g_m[2 * idx + 1] = mw;
    }
}

// ---------------- kernel 4: gather + fp16 mma + BN + SiLU, 4 CTAs/SM ---------------
// 256 threads, tile = one ho row: 64 px x 128 co. Single As, meta cp.async x2.
// smem: As[0,17408) Bs[17408,52224) M0[52224,54272) M1[54272,56320)  total 56320
#define OFF_AS   0
#define OFF_BS   17408
#define OFF_M0   52224
#define OFF_M1   54272
#define SMEM_MAIN 56320

// half-warp-wide gather: 16 lanes per pixel, 8 channels per lane, 2 px per iteration
__device__ __forceinline__ void gather_pair(int mbuf, int i, int gpix0, int lane,
                                            const char* smc, const char* xb, char* smw) {
    const uint4* meta = (const uint4*)(smc + (mbuf ? OFF_M1 : OFF_M0));
    int pix = gpix0 + 2 * i + (lane >> 4);
    int chb = (lane & 15) * 16;              // byte offset of 8-channel group
    uint4 ma = meta[2 * pix];
    uint4 mw = meta[2 * pix + 1];
    const char* xc = xb + chb;
    __half2 w00 = *(__half2*)&mw.x;
    __half2 w01 = *(__half2*)&mw.y;
    __half2 w10 = *(__half2*)&mw.z;
    __half2 w11 = *(__half2*)&mw.w;

    __half2 z = __float2half2_rn(0.f);
    __half2 r0 = z, r1 = z, r2 = z, r3 = z;
    {
        uint4 cA = *(const uint4*)(xc + ma.x + ma.z);
        uint4 cB = *(const uint4*)(xc + ma.x + ma.w);
        r0 = __hfma2(w00, ((const __half2*)&cA)[0], r0);
        r1 = __hfma2(w00, ((const __half2*)&cA)[1], r1);
        r2 = __hfma2(w00, ((const __half2*)&cA)[2], r2);
        r3 = __hfma2(w00, ((const __half2*)&cA)[3], r3);
        r0 = __hfma2(w01, ((const __half2*)&cB)[0], r0);
        r1 = __hfma2(w01, ((const __half2*)&cB)[1], r1);
        r2 = __hfma2(w01, ((const __half2*)&cB)[2], r2);
        r3 = __hfma2(w01, ((const __half2*)&cB)[3], r3);
    }
    {
        uint4 cA = *(const uint4*)(xc + ma.y + ma.z);
        uint4 cB = *(const uint4*)(xc + ma.y + ma.w);
        r0 = __hfma2(w10, ((const __half2*)&cA)[0], r0);
        r1 = __hfma2(w10, ((const __half2*)&cA)[1], r1);
        r2 = __hfma2(w10, ((const __half2*)&cA)[2], r2);
        r3 = __hfma2(w10, ((const __half2*)&cA)[3], r3);
        r0 = __hfma2(w11, ((const __half2*)&cB)[0], r0);
        r1 = __hfma2(w11, ((const __half2*)&cB)[1], r1);
        r2 = __hfma2(w11, ((const __half2*)&cB)[2], r2);
        r3 = __hfma2(w11, ((const __half2*)&cB)[3], r3);
    }
    uint4 o;
    o.x = *(const u32*)&r0;
    o.y = *(const u32*)&r1;
    o.z = *(const u32*)&r2;
    o.w = *(const u32*)&r3;
    *(uint4*)(smw + OFF_AS + pix * ROWB + chb) = o;
}

__device__ __forceinline__ void copy_bs(const __half* src_g, u32 dst_u, int tid) {
    const char* src = (const char*)src_g;
    #pragma unroll
    for (int i = 0; i < 8; i++) {
        int c   = tid + i * 256;
        int row = c >> 4;
        int c16 = c & 15;
        cp_async16(dst_u + (u32)(row * ROWB + c16 * 16), src + row * 256 + c16 * 16);
    }
}

__global__ __launch_bounds__(256, 4)
void k_main(const float* __restrict__ gamma,
            const float* __restrict__ beta,
            const float* __restrict__ rmean,
            const float* __restrict__ rvar,
            float* __restrict__ out) {
    extern __shared__ char smc[];
    u32 sbase = cvta_smem(smc);
    u32 bsU = sbase + OFF_BS;
    u32 mU0 = sbase + OFF_M0;
    u32 mU1 = sbase + OFF_M1;

    int tid  = threadIdx.x;
    int ho   = blockIdx.x;
    int n    = blockIdx.y;
    int lane = tid & 31;
    int warp = tid >> 5;
    int wm   = warp >> 2;
    int wn   = warp & 3;
    int gpix0 = warp * 8;

    const char* mbase0 = (const char*)(g_m + 2 * (((size_t)(n * PP)) * PIX_PER_N + ho * WO));
    const size_t mstride = (size_t)PIX_PER_N * 32;
    const char* xb = (const char*)(g_xh + (size_t)n * HW * CIN);

    // prologue: meta(0)->M0 + Bs(0); wait; gather(0); issue meta(1)->M1; wait
    if (tid < 128) cp_async16(mU0 + tid * 16, mbase0 + tid * 16);
    copy_bs(g_wf, bsU, tid);
    CP_COMMIT();
    CP_WAIT(0);
    __syncthreads();
    #pragma unroll
    for (int i = 0; i < 4; i++)
        gather_pair(0, i, gpix0, lane, smc, xb, smc);
    if (tid < 128) cp_async16(mU1 + tid * 16, mbase0 + mstride + tid * 16);
    CP_COMMIT();
    CP_WAIT(0);
    __syncthreads();

    float acc[2][4][4];
    #pragma unroll
    for (int mt = 0; mt < 2; mt++)
        #pragma unroll
        for (int nt = 0; nt < 4; nt++)
            #pragma unroll
            for (int i = 0; i < 4; i++) acc[mt][nt][i] = 0.f;

    int lrow = lane & 15;
    int lcol = (lane >> 4) << 4;
    // hoisted ldmatrix bases
    u32 aB0 = sbase + OFF_AS + (u32)((wm * 32 + lrow) * ROWB) + (u32)lcol;
    u32 aB1 = aB0 + 16u * ROWB;
    u32 bB0 = bsU + (u32)((wn * 32 + lrow) * ROWB) + (u32)lcol;
    u32 bB1 = bB0 + 16u * ROWB;

    for (int p = 0; p < PP; p++) {
        // ---- GEMM tap p ----
        #pragma unroll
        for (int ks = 0; ks < 8; ks++) {
            u32 kb = (u32)(ks * 32);
            u32 a[2][4], b[2][4];
            ldm4(a[0], aB0 + kb);
            ldm4(a[1], aB1 + kb);
            ldm4(b[0], bB0 + kb);
            ldm4(b[1], bB1 + kb);
            #pragma unroll
            for (int mt = 0; mt < 2; mt++)
                #pragma unroll
                for (int nt = 0; nt < 4; nt++) {
                    int pr = nt >> 1, s = nt & 1;
                    mma_f16(acc[mt][nt], a[mt], b[pr][s], b[pr][2 + s]);
                }
        }
        __syncthreads();                 // done reading As/Bs tap p
        if (p < PP - 1) {
            copy_bs(g_wf + (size_t)(p + 1) * COUT * CIN, bsU, tid);
            if (p + 2 < PP && tid < 128)
                cp_async16((((p & 1) == 0) ? mU0 : mU1) + tid * 16,
                           mbase0 + (size_t)(p + 2) * mstride + tid * 16);
            CP_COMMIT();
            // gather(p+1) from meta buf (p+1)&1 — landed in previous iteration
            #pragma unroll
            for (int i = 0; i < 4; i++)
                gather_pair((p + 1) & 1, i, gpix0, lane, smc, xb, smc);
            CP_WAIT(0);
            __syncthreads();
        }
    }

    // ---- epilogue: BN + SiLU (BN params direct from gmem; L2-hit broadcasts) ----
    #pragma unroll
    for (int mt = 0; mt < 2; mt++)
        #pragma unroll
        for (int nt = 0; nt < 4; nt++) {
            int co = wn * 32 + nt * 8 + (lane & 3) * 2;
            int px = wm * 32 + mt * 16 + (lane >> 2);
            float s0 = gamma[co]     * rsqrtf(rvar[co]     + 1e-5f);
            float s1 = gamma[co + 1] * rsqrtf(rvar[co + 1] + 1e-5f);
            float b0 = beta[co]     - rmean[co]     * s0;
            float b1 = beta[co + 1] - rmean[co + 1] * s1;
            #pragma unroll
            for (int h = 0; h < 2; h++) {
                int wo = px + h * 8;
                float y0v = acc[mt][nt][h * 2 + 0] * s0 + b0;
                float y1v = acc[mt][nt][h * 2 + 1] * s1 + b1;
                out[(((size_t)(n * COUT + co))     * HO + ho) * WO + wo] = y0v / (1.f + __expf(-y0v));
                out[(((size_t)(n * COUT + co + 1)) * HO + ho) * WO + wo] = y1v / (1.f + __expf(-y1v));
            }
        }
}

// ---------------- launch ----------------
extern "C" void kernel_launch(void* const* d_in, const int* in_sizes, int n_in,
                              void* d_out, int out_size) {
    const float* x        = (const float*)d_in[0];
    const float* offset_w = (const float*)d_in[1];
    const float* offset_b = (const float*)d_in[2];
    const float* deform_w = (const float*)d_in[3];
    const float* gamma    = (const float*)d_in[4];
    const float* beta     = (const float*)d_in[5];
    const float* rmean    = (const float*)d_in[6];
    const float* rvar     = (const float*)d_in[7];
    float* out = (float*)d_out;

    cudaFuncSetAttribute(k_offmma, cudaFuncAttributeMaxDynamicSharedMemorySize, SMEM_OFF);
    cudaFuncSetAttribute(k_main,   cudaFuncAttributeMaxDynamicSharedMemorySize, SMEM_MAIN);

    k_transpose_x<<<dim3(HW / 64, CIN / 32, NB), 256>>>(x);
    k_prep<<<(PP * COUT * CIN + PP * 32 * CIN + 255) / 256, 256>>>(deform_w, offset_w);

    k_offmma<<<dim3(HO, NB), 256, SMEM_OFF>>>(offset_b);

    k_main<<<dim3(HO, NB), 256, SMEM_MAIN>>>(gamma, beta, rmean, rvar, out);
}